// round 5
// baseline (speedup 1.0000x reference)
#include <cuda_runtime.h>
#include <math.h>

#define BB 2
#define TT 2048
#define CC 1024
#define NH 16
#define HD 64
#define BH (BB*NH)

// scratch — all tf32-encoded, fragment-permuted layouts
__device__ float g_q[(size_t)BH * TT * HD];      // [bh][t][d_perm], pre-scaled 1/8
__device__ float g_k[(size_t)BH * TT * HD];      // [bh][t][d_perm]
__device__ float g_vt[(size_t)BH * HD * TT];     // [bh][d][t_perm]  (V transposed)
__device__ float g_att[(size_t)BH * TT * HD];    // [bh][t][d_perm]
__device__ float g_xt[(size_t)BB * TT * CC];     // [m][k_perm]
__device__ float g_wqkvT[(size_t)3 * CC * CC];   // [n][k_perm]
__device__ float g_wprojT[(size_t)CC * CC];      // [n][k_perm]

// perm within each 32-k chunk: perm(k) = (k%4)*8 + (k%32)/4
__device__ __forceinline__ int dperm64(int d) {
    return (d & 32) + ((d & 3) << 3) + ((d & 31) >> 2);
}

__device__ __forceinline__ unsigned f2tf(float f) {
    unsigned u;
    asm("cvt.rna.tf32.f32 %0, %1;" : "=r"(u) : "f"(f));
    return u;
}
__device__ __forceinline__ float f2tff(float f) { return __uint_as_float(f2tf(f)); }

__device__ __forceinline__ void mma8(float* c, float a0, float a1, float a2, float a3,
                                     float b0, float b1) {
    asm volatile(
        "mma.sync.aligned.m16n8k8.row.col.f32.tf32.tf32.f32 "
        "{%0,%1,%2,%3}, {%4,%5,%6,%7}, {%8,%9}, {%0,%1,%2,%3};"
        : "+f"(c[0]), "+f"(c[1]), "+f"(c[2]), "+f"(c[3])
        : "r"(__float_as_uint(a0)), "r"(__float_as_uint(a1)),
          "r"(__float_as_uint(a2)), "r"(__float_as_uint(a3)),
          "r"(__float_as_uint(b0)), "r"(__float_as_uint(b1)));
}

__device__ __forceinline__ void cpa16(float* smem_dst, const float* gptr) {
    unsigned s = (unsigned)__cvta_generic_to_shared(smem_dst);
    asm volatile("cp.async.cg.shared.global [%0], [%1], 16;" :: "r"(s), "l"(gptr));
}
#define CP_COMMIT asm volatile("cp.async.commit_group;")
#define CP_WAIT1  asm volatile("cp.async.wait_group 1;")
#define CP_WAIT0  asm volatile("cp.async.wait_group 0;")

// ---------------------------------------------------------------------------
// pre-pass: x -> [m][k_perm] tf32
// ---------------------------------------------------------------------------
__global__ __launch_bounds__(256) void perm_x_kernel(const float* __restrict__ in,
                                                     float* __restrict__ out)
{
    size_t o = ((size_t)blockIdx.x * 256 + threadIdx.x) * 4;
    size_t row = o >> 10;
    int col = (int)(o & 1023);
    int chunk = col & ~31, p = col & 31;
    float r[4];
    #pragma unroll
    for (int j = 0; j < 4; j++) {
        int pj = p + j;
        int k = ((pj & 7) << 2) + (pj >> 3);
        r[j] = f2tff(in[(row << 10) + chunk + k]);
    }
    *(float4*)&out[o] = make_float4(r[0], r[1], r[2], r[3]);
}

// pre-pass: W[K=1024][N] -> out[N][1024 k_perm] tf32 (tiled transpose)
__global__ __launch_bounds__(256) void transpose_perm_kernel(const float* __restrict__ in,
                                                             float* __restrict__ out,
                                                             int N)
{
    __shared__ float t[32][33];
    const int k0 = blockIdx.y << 5, n0 = blockIdx.x << 5;
    const int tx = threadIdx.x & 31, ty = threadIdx.x >> 5;
    #pragma unroll
    for (int i = 0; i < 4; i++)
        t[ty + 8 * i][tx] = f2tff(in[(size_t)(k0 + ty + 8 * i) * N + n0 + tx]);
    __syncthreads();
    const int pp = ((tx & 3) << 3) + (tx >> 2);
    #pragma unroll
    for (int i = 0; i < 4; i++)
        out[(size_t)(n0 + ty + 8 * i) * 1024 + k0 + pp] = t[tx][ty + 8 * i];
}

// ---------------------------------------------------------------------------
// GEMM microkernel pieces. Block tile 128x128, BK=32, 2-stage cp.async.
// A smem [128 m][36], B smem [128 n][36], both k-permuted.
// ---------------------------------------------------------------------------
#define TS 36
#define TSZ (128*TS)

#define GEMM_COMPUTE(Asb, Bsb)                                                   \
    _Pragma("unroll")                                                            \
    for (int kp = 0; kp < 2; kp++) {                                             \
        float4 alo[4], ahi[4], bf[4];                                            \
        _Pragma("unroll")                                                        \
        for (int tm = 0; tm < 4; tm++) {                                         \
            int r = wm + tm * 16 + gi;                                           \
            alo[tm] = *(const float4*)&(Asb)[r * TS + gc * 8 + kp * 4];           \
            ahi[tm] = *(const float4*)&(Asb)[(r + 8) * TS + gc * 8 + kp * 4];     \
        }                                                                        \
        _Pragma("unroll")                                                        \
        for (int tn = 0; tn < 4; tn++) {                                         \
            int n = wn + tn * 8 + gi;                                            \
            bf[tn] = *(const float4*)&(Bsb)[n * TS + gc * 8 + kp * 4];            \
        }                                                                        \
        _Pragma("unroll")                                                        \
        for (int tm = 0; tm < 4; tm++)                                           \
            _Pragma("unroll")                                                    \
            for (int tn = 0; tn < 4; tn++) {                                     \
                mma8(C[tm][tn], alo[tm].x, ahi[tm].x, alo[tm].y, ahi[tm].y,      \
                     bf[tn].x, bf[tn].y);                                        \
                mma8(C[tm][tn], alo[tm].z, ahi[tm].z, alo[tm].w, ahi[tm].w,      \
                     bf[tn].z, bf[tn].w);                                        \
            }                                                                    \
    }

// ---------------------------------------------------------------------------
// Kernel 1: QKV GEMM
// ---------------------------------------------------------------------------
__global__ __launch_bounds__(256) void qkv_mma_kernel(const float* __restrict__ bias)
{
    extern __shared__ float smem[];
    float* As = smem;              // [2][128][36]
    float* Bs = smem + 2 * TSZ;

    const int tid  = threadIdx.x;
    const int lane = tid & 31;
    const int warp = tid >> 5;
    const int gi = lane >> 2, gc = lane & 3;
    const int wm = (warp >> 2) * 64;
    const int wn = (warp & 3) * 32;
    const int m0 = blockIdx.y * 128, n0 = blockIdx.x * 128;

    float C[4][4][4] = {};

#define QKV_LOAD(s, k0)                                                          \
    {                                                                            \
        _Pragma("unroll")                                                        \
        for (int i = 0; i < 4; i++) {                                            \
            int f4 = i * 256 + tid;                                              \
            int row = f4 >> 3, col = (f4 & 7) << 2;                              \
            cpa16(&As[(s)*TSZ + row * TS + col],                                 \
                  &g_xt[(size_t)(m0 + row) * CC + (k0) + col]);                  \
            cpa16(&Bs[(s)*TSZ + row * TS + col],                                 \
                  &g_wqkvT[(size_t)(n0 + row) * CC + (k0) + col]);               \
        }                                                                        \
        CP_COMMIT;                                                               \
    }

    QKV_LOAD(0, 0);
    for (int it = 0; it < 32; it++) {
        const int s = it & 1;
        if (it + 1 < 32) { QKV_LOAD(s ^ 1, (it + 1) * 32); CP_WAIT1; }
        else             { CP_WAIT0; }
        __syncthreads();
        const float* Asb = As + s * TSZ;
        const float* Bsb = Bs + s * TSZ;
        GEMM_COMPUTE(Asb, Bsb);
        __syncthreads();
    }

    #pragma unroll
    for (int tm = 0; tm < 4; tm++) {
        #pragma unroll
        for (int tn = 0; tn < 4; tn++) {
            #pragma unroll
            for (int e = 0; e < 4; e++) {
                int m = m0 + wm + tm * 16 + gi + ((e >= 2) ? 8 : 0);
                int n = n0 + wn + tn * 8 + 2 * gc + (e & 1);
                float v = C[tm][tn][e] + bias[n];
                int b = m >> 11, t = m & 2047;
                int h = n / 192;
                int r = n - h * 192;
                int d = r & 63;
                int bh = (b << 4) + h;
                if (r < 64) {
                    g_q[((size_t)bh << 17) + ((size_t)t << 6) + dperm64(d)] =
                        f2tff(v * 0.125f);
                } else if (r < 128) {
                    g_k[((size_t)bh << 17) + ((size_t)t << 6) + dperm64(d)] = f2tff(v);
                } else {
                    int tp = (t & ~31) + ((t & 3) << 3) + ((t & 31) >> 2);
                    g_vt[((size_t)(bh * 64 + d) << 11) + tp] = f2tff(v);
                }
            }
        }
    }
}

// ---------------------------------------------------------------------------
// Kernel 2: causal flash attention. 256 thr, 128-query tile, 64-key tiles.
// Block x handles qt = x and qt = 15-x (load balance). All operands permuted.
// ---------------------------------------------------------------------------
#define APAD 68
#define KV_SZ (64*APAD)

__global__ __launch_bounds__(256) void attn_mma_kernel()
{
    extern __shared__ float sm[];
    float* sK  = sm;                 // [2][64 key][68 dim_perm]
    float* sVt = sm + 2 * KV_SZ;     // [2][64 dim][68 key_perm]
    float* sP  = sm + 4 * KV_SZ;     // [128][68]  Q then P

    const int bh = blockIdx.y;
    const int tid = threadIdx.x;
    const int lane = tid & 31;
    const int warp = tid >> 5;
    const int gi = lane >> 2, gc = lane & 3;
    const int i0 = warp * 16 + gi;

    const float* Kg = g_k + ((size_t)bh << 17);
    const float* Vtg = g_vt + ((size_t)bh << 17);

#define KV_LOAD(s, kt)                                                        \
    {                                                                         \
        _Pragma("unroll")                                                     \
        for (int i = 0; i < 4; i++) {                                         \
            int f4 = i * 256 + tid;                                           \
            int r = f4 >> 4, c = (f4 & 15) << 2;                              \
            cpa16(&sK[((s)*64 + r) * APAD + c],                               \
                  &Kg[(size_t)(((kt) << 6) + r) * HD + c]);                   \
            cpa16(&sVt[((s)*64 + r) * APAD + c],                              \
                  &Vtg[((size_t)r << 11) + ((kt) << 6) + c]);                 \
        }                                                                     \
        CP_COMMIT;                                                            \
    }

    for (int pi = 0; pi < 2; pi++) {
        const int qt = pi ? (15 - (int)blockIdx.x) : (int)blockIdx.x;
        const int ktmax = 2 * qt + 1;
        const float* Qg = g_q + ((size_t)bh << 17) + ((size_t)qt << 13);

        __syncthreads();
        // stage Q
        #pragma unroll
        for (int i = 0; i < 8; i++) {
            int f4 = i * 256 + tid;
            int r = f4 >> 4, c = (f4 & 15) << 2;
            cpa16(&sP[r * APAD + c], &Qg[(r << 6) + c]);
        }
        CP_COMMIT;
        KV_LOAD(0, 0);

        float4 qlo[4], qhi[4];    // [c*2+h]
        float O[8][4] = {};
        float m0r = -1e30f, m1r = -1e30f, l0r = 0.f, l1r = 0.f;

        for (int kt = 0; kt <= ktmax; kt++) {
            const int s = kt & 1;
            if (kt < ktmax) { KV_LOAD(s ^ 1, kt + 1); CP_WAIT1; }
            else            { CP_WAIT0; }
            __syncthreads();

            if (kt == 0) {
                #pragma unroll
                for (int c = 0; c < 2; c++)
                    #pragma unroll
                    for (int h = 0; h < 2; h++) {
                        qlo[c * 2 + h] = *(const float4*)&sP[i0 * APAD + c * 32 + gc * 8 + h * 4];
                        qhi[c * 2 + h] = *(const float4*)&sP[(i0 + 8) * APAD + c * 32 + gc * 8 + h * 4];
                    }
            }

            const bool active = (kt * 64 <= qt * 128 + warp * 16 + 15);
            if (active) {
                const float* sKb  = sK + s * KV_SZ;
                const float* sVtb = sVt + s * KV_SZ;

                // ---- S = Q @ K^T ----
                float S[8][4] = {};
                #pragma unroll
                for (int c = 0; c < 2; c++)
                    #pragma unroll
                    for (int h = 0; h < 2; h++) {
                        float4 qL = qlo[c * 2 + h], qH = qhi[c * 2 + h];
                        #pragma unroll
                        for (int nt = 0; nt < 8; nt++) {
                            int n = nt * 8 + gi;
                            float4 kb = *(const float4*)&sKb[n * APAD + c * 32 + gc * 8 + h * 4];
                            mma8(S[nt], qL.x, qH.x, qL.y, qH.y, kb.x, kb.y);
                            mma8(S[nt], qL.z, qH.z, qL.w, qH.w, kb.z, kb.w);
                        }
                    }

                if (kt >= 2 * qt) {
                    int ig0 = qt * 128 + i0;
                    #pragma unroll
                    for (int nt = 0; nt < 8; nt++) {
                        int j0 = kt * 64 + nt * 8 + 2 * gc;
                        if (j0 > ig0)         S[nt][0] = -1e30f;
                        if (j0 + 1 > ig0)     S[nt][1] = -1e30f;
                        if (j0 > ig0 + 8)     S[nt][2] = -1e30f;
                        if (j0 + 1 > ig0 + 8) S[nt][3] = -1e30f;
                    }
                }

                float mx0 = -1e30f, mx1 = -1e30f;
                #pragma unroll
                for (int nt = 0; nt < 8; nt++) {
                    mx0 = fmaxf(mx0, fmaxf(S[nt][0], S[nt][1]));
                    mx1 = fmaxf(mx1, fmaxf(S[nt][2], S[nt][3]));
                }
                mx0 = fmaxf(mx0, __shfl_xor_sync(0xffffffffu, mx0, 1));
                mx0 = fmaxf(mx0, __shfl_xor_sync(0xffffffffu, mx0, 2));
                mx1 = fmaxf(mx1, __shfl_xor_sync(0xffffffffu, mx1, 1));
                mx1 = fmaxf(mx1, __shfl_xor_sync(0xffffffffu, mx1, 2));

                float mn0 = fmaxf(m0r, mx0), mn1 = fmaxf(m1r, mx1);
                float c0 = __expf(m0r - mn0), c1 = __expf(m1r - mn1);

                float ls0 = 0.f, ls1 = 0.f;
                #pragma unroll
                for (int nt = 0; nt < 8; nt++) {
                    float p0 = __expf(S[nt][0] - mn0);
                    float p1 = __expf(S[nt][1] - mn0);
                    float p2 = __expf(S[nt][2] - mn1);
                    float p3 = __expf(S[nt][3] - mn1);
                    ls0 += p0 + p1;
                    ls1 += p2 + p3;
                    // key-permuted P store
                    int chunk = (nt >> 2) << 5;
                    int pos0 = chunk + (((2 * gc) & 3) << 3) + 2 * (nt & 3) + (gc >> 1);
                    sP[i0 * APAD + pos0]           = f2tff(p0);
                    sP[i0 * APAD + pos0 + 8]       = f2tff(p1);
                    sP[(i0 + 8) * APAD + pos0]     = f2tff(p2);
                    sP[(i0 + 8) * APAD + pos0 + 8] = f2tff(p3);
                }
                ls0 += __shfl_xor_sync(0xffffffffu, ls0, 1);
                ls0 += __shfl_xor_sync(0xffffffffu, ls0, 2);
                ls1 += __shfl_xor_sync(0xffffffffu, ls1, 1);
                ls1 += __shfl_xor_sync(0xffffffffu, ls1, 2);
                l0r = l0r * c0 + ls0;
                l1r = l1r * c1 + ls1;
                m0r = mn0; m1r = mn1;

                #pragma unroll
                for (int nt = 0; nt < 8; nt++) {
                    O[nt][0] *= c0; O[nt][1] *= c0;
                    O[nt][2] *= c1; O[nt][3] *= c1;
                }

                __syncwarp();

                // ---- O += P @ V  (B = V^T, key-permuted) ----
                #pragma unroll
                for (int c = 0; c < 2; c++)
                    #pragma unroll
                    for (int h = 0; h < 2; h++) {
                        float4 pL = *(const float4*)&sP[i0 * APAD + c * 32 + gc * 8 + h * 4];
                        float4 pH = *(const float4*)&sP[(i0 + 8) * APAD + c * 32 + gc * 8 + h * 4];
                        #pragma unroll
                        for (int nt = 0; nt < 8; nt++) {
                            int n = nt * 8 + gi;
                            float4 vb = *(const float4*)&sVtb[n * APAD + c * 32 + gc * 8 + h * 4];
                            mma8(O[nt], pL.x, pH.x, pL.y, pH.y, vb.x, vb.y);
                            mma8(O[nt], pL.z, pH.z, pL.w, pH.w, vb.z, vb.w);
                        }
                    }
                __syncwarp();
            }
            __syncthreads();
        }

        float inv0 = 1.f / l0r, inv1 = 1.f / l1r;
        float* Og = g_att + ((size_t)bh << 17) + ((size_t)qt << 13);
        #pragma unroll
        for (int nt = 0; nt < 8; nt++) {
            int d0 = nt * 8 + 2 * gc;
            int dp = dperm64(d0);
            Og[(i0 << 6) + dp]           = f2tff(O[nt][0] * inv0);
            Og[(i0 << 6) + dp + 8]       = f2tff(O[nt][1] * inv0);
            Og[((i0 + 8) << 6) + dp]     = f2tff(O[nt][2] * inv1);
            Og[((i0 + 8) << 6) + dp + 8] = f2tff(O[nt][3] * inv1);
        }
    }
}

// ---------------------------------------------------------------------------
// Kernel 3: proj GEMM
// ---------------------------------------------------------------------------
__global__ __launch_bounds__(256) void proj_mma_kernel(const float* __restrict__ bias,
                                                       float* __restrict__ out)
{
    extern __shared__ float smem[];
    float* As = smem;
    float* Bs = smem + 2 * TSZ;

    const int tid  = threadIdx.x;
    const int lane = tid & 31;
    const int warp = tid >> 5;
    const int gi = lane >> 2, gc = lane & 3;
    const int wm = (warp >> 2) * 64;
    const int wn = (warp & 3) * 32;
    const int m0 = blockIdx.y * 128, n0 = blockIdx.x * 128;

    float C[4][4][4] = {};

#define PROJ_LOAD(s, k0)                                                          \
    {                                                                             \
        int hh = (k0) >> 6, dbase = (k0) & 63;                                    \
        _Pragma("unroll")                                                         \
        for (int i = 0; i < 4; i++) {                                            \
            int f4 = i * 256 + tid;                                              \
            int row = f4 >> 3, col = (f4 & 7) << 2;                              \
            int m = m0 + row;                                                    \
            int b = m >> 11, t = m & 2047;                                       \
            cpa16(&As[(s)*TSZ + row * TS + col],                                 \
                  &g_att[(((size_t)((b << 4) + hh) << 11) + t) * HD + dbase + col]); \
            cpa16(&Bs[(s)*TSZ + row * TS + col],                                 \
                  &g_wprojT[(size_t)(n0 + row) * CC + (k0) + col]);              \
        }                                                                        \
        CP_COMMIT;                                                               \
    }

    PROJ_LOAD(0, 0);
    for (int it = 0; it < 32; it++) {
        const int s = it & 1;
        if (it + 1 < 32) { PROJ_LOAD(s ^ 1, (it + 1) * 32); CP_WAIT1; }
        else             { CP_WAIT0; }
        __syncthreads();
        const float* Asb = As + s * TSZ;
        const float* Bsb = Bs + s * TSZ;
        GEMM_COMPUTE(Asb, Bsb);
        __syncthreads();
    }

    #pragma unroll
    for (int tm = 0; tm < 4; tm++) {
        #pragma unroll
        for (int tn = 0; tn < 4; tn++) {
            #pragma unroll
            for (int e = 0; e < 4; e++) {
                int m = m0 + wm + tm * 16 + gi + ((e >= 2) ? 8 : 0);
                int n = n0 + wn + tn * 8 + 2 * gc + (e & 1);
                out[(size_t)m * CC + n] = C[tm][tn][e] + bias[n];
            }
        }
    }
}

// ---------------------------------------------------------------------------
extern "C" void kernel_launch(void* const* d_in, const int* in_sizes, int n_in,
                              void* d_out, int out_size)
{
    const float* x     = (const float*)d_in[0];
    const float* Wqkv  = (const float*)d_in[1];
    const float* bqkv  = (const float*)d_in[2];
    const float* Wproj = (const float*)d_in[3];
    const float* bproj = (const float*)d_in[4];
    float* out = (float*)d_out;

    const int GEMM_SMEM = 4 * TSZ * 4;                       // 73728 B
    const int ATTN_SMEM = (4 * KV_SZ + 128 * APAD) * 4;      // 104448 B
    cudaFuncSetAttribute(qkv_mma_kernel,
                         cudaFuncAttributeMaxDynamicSharedMemorySize, GEMM_SMEM);
    cudaFuncSetAttribute(proj_mma_kernel,
                         cudaFuncAttributeMaxDynamicSharedMemorySize, GEMM_SMEM);
    cudaFuncSetAttribute(attn_mma_kernel,
                         cudaFuncAttributeMaxDynamicSharedMemorySize, ATTN_SMEM);

    float* xt; float* wq; float* wp;
    cudaGetSymbolAddress((void**)&xt, g_xt);
    cudaGetSymbolAddress((void**)&wq, g_wqkvT);
    cudaGetSymbolAddress((void**)&wp, g_wprojT);

    perm_x_kernel<<<4096, 256>>>(x, xt);                                  // 4096x1024
    transpose_perm_kernel<<<dim3(96, 32), 256>>>(Wqkv, wq, 3 * CC);       // -> [3072][1024]
    transpose_perm_kernel<<<dim3(32, 32), 256>>>(Wproj, wp, CC);          // -> [1024][1024]

    qkv_mma_kernel<<<dim3(24, 32), 256, GEMM_SMEM>>>(bqkv);
    attn_mma_kernel<<<dim3(8, 32), 256, ATTN_SMEM>>>();
    proj_mma_kernel<<<dim3(8, 32), 256, GEMM_SMEM>>>(bproj, out);
}

// round 6
// speedup vs baseline: 1.1511x; 1.1511x over previous
#include <cuda_runtime.h>
#include <math.h>

#define BB 2
#define TT 2048
#define CC 1024
#define NH 16
#define HD 64
#define BH (BB*NH)

// scratch — all tf32-encoded, fragment-permuted layouts
__device__ float g_q[(size_t)BH * TT * HD];      // [bh][t][d_perm], pre-scaled 1/8
__device__ float g_k[(size_t)BH * TT * HD];      // [bh][t][d_perm]
__device__ float g_vt[(size_t)BH * HD * TT];     // [bh][d][t_perm]  (V transposed)
__device__ float g_att[(size_t)BH * TT * HD];    // [bh][t][d_perm]
__device__ float g_xt[(size_t)BB * TT * CC];     // [m][k_perm]
__device__ float g_wqkvT[(size_t)3 * CC * CC];   // [n][k_perm]
__device__ float g_wprojT[(size_t)CC * CC];      // [n][k_perm]

// perm within each 32-k chunk: perm(k) = (k%4)*8 + (k%32)/4
__device__ __forceinline__ int dperm64(int d) {
    return (d & 32) + ((d & 3) << 3) + ((d & 31) >> 2);
}

__device__ __forceinline__ unsigned f2tf(float f) {
    unsigned u;
    asm("cvt.rna.tf32.f32 %0, %1;" : "=r"(u) : "f"(f));
    return u;
}
__device__ __forceinline__ float f2tff(float f) { return __uint_as_float(f2tf(f)); }

__device__ __forceinline__ void mma8(float* c, float a0, float a1, float a2, float a3,
                                     float b0, float b1) {
    asm volatile(
        "mma.sync.aligned.m16n8k8.row.col.f32.tf32.tf32.f32 "
        "{%0,%1,%2,%3}, {%4,%5,%6,%7}, {%8,%9}, {%0,%1,%2,%3};"
        : "+f"(c[0]), "+f"(c[1]), "+f"(c[2]), "+f"(c[3])
        : "r"(__float_as_uint(a0)), "r"(__float_as_uint(a1)),
          "r"(__float_as_uint(a2)), "r"(__float_as_uint(a3)),
          "r"(__float_as_uint(b0)), "r"(__float_as_uint(b1)));
}

__device__ __forceinline__ void cpa16(float* smem_dst, const float* gptr) {
    unsigned s = (unsigned)__cvta_generic_to_shared(smem_dst);
    asm volatile("cp.async.cg.shared.global [%0], [%1], 16;" :: "r"(s), "l"(gptr));
}
#define CP_COMMIT asm volatile("cp.async.commit_group;")
#define CP_WAIT1  asm volatile("cp.async.wait_group 1;")
#define CP_WAIT0  asm volatile("cp.async.wait_group 0;")

// ---------------------------------------------------------------------------
// pre-pass: x -> [m][k_perm] tf32
// ---------------------------------------------------------------------------
__global__ __launch_bounds__(256) void perm_x_kernel(const float* __restrict__ in,
                                                     float* __restrict__ out)
{
    size_t o = ((size_t)blockIdx.x * 256 + threadIdx.x) * 4;
    size_t row = o >> 10;
    int col = (int)(o & 1023);
    int chunk = col & ~31, p = col & 31;
    float r[4];
    #pragma unroll
    for (int j = 0; j < 4; j++) {
        int pj = p + j;
        int k = ((pj & 7) << 2) + (pj >> 3);
        r[j] = f2tff(in[(row << 10) + chunk + k]);
    }
    *(float4*)&out[o] = make_float4(r[0], r[1], r[2], r[3]);
}

// pre-pass: W[K=1024][N] -> out[N][1024 k_perm] tf32 (tiled transpose)
__global__ __launch_bounds__(256) void transpose_perm_kernel(const float* __restrict__ in,
                                                             float* __restrict__ out,
                                                             int N)
{
    __shared__ float t[32][33];
    const int k0 = blockIdx.y << 5, n0 = blockIdx.x << 5;
    const int tx = threadIdx.x & 31, ty = threadIdx.x >> 5;
    #pragma unroll
    for (int i = 0; i < 4; i++)
        t[ty + 8 * i][tx] = f2tff(in[(size_t)(k0 + ty + 8 * i) * N + n0 + tx]);
    __syncthreads();
    const int pp = ((tx & 3) << 3) + (tx >> 2);
    #pragma unroll
    for (int i = 0; i < 4; i++)
        out[(size_t)(n0 + ty + 8 * i) * 1024 + k0 + pp] = t[tx][ty + 8 * i];
}

// ---------------------------------------------------------------------------
// GEMM microkernel pieces. Block tile 128x128, BK=32, 2-stage cp.async.
// A smem [128 m][36], B smem [128 n][36], both k-permuted.
// ---------------------------------------------------------------------------
#define TS 36
#define TSZ (128*TS)

#define GEMM_COMPUTE(Asb, Bsb)                                                   \
    _Pragma("unroll")                                                            \
    for (int kp = 0; kp < 2; kp++) {                                             \
        float4 alo[4], ahi[4], bf[4];                                            \
        _Pragma("unroll")                                                        \
        for (int tm = 0; tm < 4; tm++) {                                         \
            int r = wm + tm * 16 + gi;                                           \
            alo[tm] = *(const float4*)&(Asb)[r * TS + gc * 8 + kp * 4];           \
            ahi[tm] = *(const float4*)&(Asb)[(r + 8) * TS + gc * 8 + kp * 4];     \
        }                                                                        \
        _Pragma("unroll")                                                        \
        for (int tn = 0; tn < 4; tn++) {                                         \
            int n = wn + tn * 8 + gi;                                            \
            bf[tn] = *(const float4*)&(Bsb)[n * TS + gc * 8 + kp * 4];            \
        }                                                                        \
        _Pragma("unroll")                                                        \
        for (int tm = 0; tm < 4; tm++)                                           \
            _Pragma("unroll")                                                    \
            for (int tn = 0; tn < 4; tn++) {                                     \
                mma8(C[tm][tn], alo[tm].x, ahi[tm].x, alo[tm].y, ahi[tm].y,      \
                     bf[tn].x, bf[tn].y);                                        \
                mma8(C[tm][tn], alo[tm].z, ahi[tm].z, alo[tm].w, ahi[tm].w,      \
                     bf[tn].z, bf[tn].w);                                        \
            }                                                                    \
    }

// ---------------------------------------------------------------------------
// Kernel 1: QKV GEMM
// ---------------------------------------------------------------------------
__global__ __launch_bounds__(256, 2) void qkv_mma_kernel(const float* __restrict__ bias)
{
    extern __shared__ float smem[];
    float* As = smem;              // [2][128][36]
    float* Bs = smem + 2 * TSZ;

    const int tid  = threadIdx.x;
    const int lane = tid & 31;
    const int warp = tid >> 5;
    const int gi = lane >> 2, gc = lane & 3;
    const int wm = (warp >> 2) * 64;
    const int wn = (warp & 3) * 32;
    const int m0 = blockIdx.y * 128, n0 = blockIdx.x * 128;

    float C[4][4][4] = {};

#define QKV_LOAD(s, k0)                                                          \
    {                                                                            \
        _Pragma("unroll")                                                        \
        for (int i = 0; i < 4; i++) {                                            \
            int f4 = i * 256 + tid;                                              \
            int row = f4 >> 3, col = (f4 & 7) << 2;                              \
            cpa16(&As[(s)*TSZ + row * TS + col],                                 \
                  &g_xt[(size_t)(m0 + row) * CC + (k0) + col]);                  \
            cpa16(&Bs[(s)*TSZ + row * TS + col],                                 \
                  &g_wqkvT[(size_t)(n0 + row) * CC + (k0) + col]);               \
        }                                                                        \
        CP_COMMIT;                                                               \
    }

    QKV_LOAD(0, 0);
    for (int it = 0; it < 32; it++) {
        const int s = it & 1;
        if (it + 1 < 32) { QKV_LOAD(s ^ 1, (it + 1) * 32); CP_WAIT1; }
        else             { CP_WAIT0; }
        __syncthreads();
        const float* Asb = As + s * TSZ;
        const float* Bsb = Bs + s * TSZ;
        GEMM_COMPUTE(Asb, Bsb);
        __syncthreads();
    }

    #pragma unroll
    for (int tm = 0; tm < 4; tm++) {
        #pragma unroll
        for (int tn = 0; tn < 4; tn++) {
            #pragma unroll
            for (int e = 0; e < 4; e++) {
                int m = m0 + wm + tm * 16 + gi + ((e >= 2) ? 8 : 0);
                int n = n0 + wn + tn * 8 + 2 * gc + (e & 1);
                float v = C[tm][tn][e] + bias[n];
                int b = m >> 11, t = m & 2047;
                int h = n / 192;
                int r = n - h * 192;
                int d = r & 63;
                int bh = (b << 4) + h;
                if (r < 64) {
                    g_q[((size_t)bh << 17) + ((size_t)t << 6) + dperm64(d)] =
                        f2tff(v * 0.125f);
                } else if (r < 128) {
                    g_k[((size_t)bh << 17) + ((size_t)t << 6) + dperm64(d)] = f2tff(v);
                } else {
                    int tp = (t & ~31) + ((t & 3) << 3) + ((t & 31) >> 2);
                    g_vt[((size_t)(bh * 64 + d) << 11) + tp] = f2tff(v);
                }
            }
        }
    }
}

// ---------------------------------------------------------------------------
// Kernel 2: causal flash attention. 256 thr, 128-query tile, 64-key tiles.
// Block x handles qt = x and qt = 15-x (load balance). All operands permuted.
// ---------------------------------------------------------------------------
#define APAD 68
#define KV_SZ (64*APAD)

__global__ __launch_bounds__(256, 2) void attn_mma_kernel()
{
    extern __shared__ float sm[];
    float* sK  = sm;                 // [2][64 key][68 dim_perm]
    float* sVt = sm + 2 * KV_SZ;     // [2][64 dim][68 key_perm]
    float* sP  = sm + 4 * KV_SZ;     // [128][68]  Q then P

    const int bh = blockIdx.y;
    const int tid = threadIdx.x;
    const int lane = tid & 31;
    const int warp = tid >> 5;
    const int gi = lane >> 2, gc = lane & 3;
    const int i0 = warp * 16 + gi;

    const float* Kg = g_k + ((size_t)bh << 17);
    const float* Vtg = g_vt + ((size_t)bh << 17);

#define KV_LOAD(s, kt)                                                        \
    {                                                                         \
        _Pragma("unroll")                                                     \
        for (int i = 0; i < 4; i++) {                                         \
            int f4 = i * 256 + tid;                                           \
            int r = f4 >> 4, c = (f4 & 15) << 2;                              \
            cpa16(&sK[((s)*64 + r) * APAD + c],                               \
                  &Kg[(size_t)(((kt) << 6) + r) * HD + c]);                   \
            cpa16(&sVt[((s)*64 + r) * APAD + c],                              \
                  &Vtg[((size_t)r << 11) + ((kt) << 6) + c]);                 \
        }                                                                     \
        CP_COMMIT;                                                            \
    }

    for (int pi = 0; pi < 2; pi++) {
        const int qt = pi ? (15 - (int)blockIdx.x) : (int)blockIdx.x;
        const int ktmax = 2 * qt + 1;
        const float* Qg = g_q + ((size_t)bh << 17) + ((size_t)qt << 13);

        __syncthreads();
        // stage Q
        #pragma unroll
        for (int i = 0; i < 8; i++) {
            int f4 = i * 256 + tid;
            int r = f4 >> 4, c = (f4 & 15) << 2;
            cpa16(&sP[r * APAD + c], &Qg[(r << 6) + c]);
        }
        CP_COMMIT;
        KV_LOAD(0, 0);

        float4 qlo[4], qhi[4];    // [c*2+h]
        float O[8][4] = {};
        float m0r = -1e30f, m1r = -1e30f, l0r = 0.f, l1r = 0.f;

        for (int kt = 0; kt <= ktmax; kt++) {
            const int s = kt & 1;
            if (kt < ktmax) { KV_LOAD(s ^ 1, kt + 1); CP_WAIT1; }
            else            { CP_WAIT0; }
            __syncthreads();

            if (kt == 0) {
                #pragma unroll
                for (int c = 0; c < 2; c++)
                    #pragma unroll
                    for (int h = 0; h < 2; h++) {
                        qlo[c * 2 + h] = *(const float4*)&sP[i0 * APAD + c * 32 + gc * 8 + h * 4];
                        qhi[c * 2 + h] = *(const float4*)&sP[(i0 + 8) * APAD + c * 32 + gc * 8 + h * 4];
                    }
            }

            const bool active = (kt * 64 <= qt * 128 + warp * 16 + 15);
            if (active) {
                const float* sKb  = sK + s * KV_SZ;
                const float* sVtb = sVt + s * KV_SZ;

                // ---- S = Q @ K^T ----
                float S[8][4] = {};
                #pragma unroll
                for (int c = 0; c < 2; c++)
                    #pragma unroll
                    for (int h = 0; h < 2; h++) {
                        float4 qL = qlo[c * 2 + h], qH = qhi[c * 2 + h];
                        #pragma unroll
                        for (int nt = 0; nt < 8; nt++) {
                            int n = nt * 8 + gi;
                            float4 kb = *(const float4*)&sKb[n * APAD + c * 32 + gc * 8 + h * 4];
                            mma8(S[nt], qL.x, qH.x, qL.y, qH.y, kb.x, kb.y);
                            mma8(S[nt], qL.z, qH.z, qL.w, qH.w, kb.z, kb.w);
                        }
                    }

                if (kt >= 2 * qt) {
                    int ig0 = qt * 128 + i0;
                    #pragma unroll
                    for (int nt = 0; nt < 8; nt++) {
                        int j0 = kt * 64 + nt * 8 + 2 * gc;
                        if (j0 > ig0)         S[nt][0] = -1e30f;
                        if (j0 + 1 > ig0)     S[nt][1] = -1e30f;
                        if (j0 > ig0 + 8)     S[nt][2] = -1e30f;
                        if (j0 + 1 > ig0 + 8) S[nt][3] = -1e30f;
                    }
                }

                float mx0 = -1e30f, mx1 = -1e30f;
                #pragma unroll
                for (int nt = 0; nt < 8; nt++) {
                    mx0 = fmaxf(mx0, fmaxf(S[nt][0], S[nt][1]));
                    mx1 = fmaxf(mx1, fmaxf(S[nt][2], S[nt][3]));
                }
                mx0 = fmaxf(mx0, __shfl_xor_sync(0xffffffffu, mx0, 1));
                mx0 = fmaxf(mx0, __shfl_xor_sync(0xffffffffu, mx0, 2));
                mx1 = fmaxf(mx1, __shfl_xor_sync(0xffffffffu, mx1, 1));
                mx1 = fmaxf(mx1, __shfl_xor_sync(0xffffffffu, mx1, 2));

                float mn0 = fmaxf(m0r, mx0), mn1 = fmaxf(m1r, mx1);
                float c0 = __expf(m0r - mn0), c1 = __expf(m1r - mn1);

                float ls0 = 0.f, ls1 = 0.f;
                #pragma unroll
                for (int nt = 0; nt < 8; nt++) {
                    float p0 = __expf(S[nt][0] - mn0);
                    float p1 = __expf(S[nt][1] - mn0);
                    float p2 = __expf(S[nt][2] - mn1);
                    float p3 = __expf(S[nt][3] - mn1);
                    ls0 += p0 + p1;
                    ls1 += p2 + p3;
                    // key-permuted P store
                    int chunk = (nt >> 2) << 5;
                    int pos0 = chunk + (((2 * gc) & 3) << 3) + 2 * (nt & 3) + (gc >> 1);
                    sP[i0 * APAD + pos0]           = f2tff(p0);
                    sP[i0 * APAD + pos0 + 8]       = f2tff(p1);
                    sP[(i0 + 8) * APAD + pos0]     = f2tff(p2);
                    sP[(i0 + 8) * APAD + pos0 + 8] = f2tff(p3);
                }
                ls0 += __shfl_xor_sync(0xffffffffu, ls0, 1);
                ls0 += __shfl_xor_sync(0xffffffffu, ls0, 2);
                ls1 += __shfl_xor_sync(0xffffffffu, ls1, 1);
                ls1 += __shfl_xor_sync(0xffffffffu, ls1, 2);
                l0r = l0r * c0 + ls0;
                l1r = l1r * c1 + ls1;
                m0r = mn0; m1r = mn1;

                #pragma unroll
                for (int nt = 0; nt < 8; nt++) {
                    O[nt][0] *= c0; O[nt][1] *= c0;
                    O[nt][2] *= c1; O[nt][3] *= c1;
                }

                __syncwarp();

                // ---- O += P @ V  (B = V^T, key-permuted) ----
                #pragma unroll
                for (int c = 0; c < 2; c++)
                    #pragma unroll
                    for (int h = 0; h < 2; h++) {
                        float4 pL = *(const float4*)&sP[i0 * APAD + c * 32 + gc * 8 + h * 4];
                        float4 pH = *(const float4*)&sP[(i0 + 8) * APAD + c * 32 + gc * 8 + h * 4];
                        #pragma unroll
                        for (int nt = 0; nt < 8; nt++) {
                            int n = nt * 8 + gi;
                            float4 vb = *(const float4*)&sVtb[n * APAD + c * 32 + gc * 8 + h * 4];
                            mma8(O[nt], pL.x, pH.x, pL.y, pH.y, vb.x, vb.y);
                            mma8(O[nt], pL.z, pH.z, pL.w, pH.w, vb.z, vb.w);
                        }
                    }
                __syncwarp();
            }
            __syncthreads();
        }

        float inv0 = 1.f / l0r, inv1 = 1.f / l1r;
        float* Og = g_att + ((size_t)bh << 17) + ((size_t)qt << 13);
        #pragma unroll
        for (int nt = 0; nt < 8; nt++) {
            int d0 = nt * 8 + 2 * gc;
            int dp = dperm64(d0);
            Og[(i0 << 6) + dp]           = f2tff(O[nt][0] * inv0);
            Og[(i0 << 6) + dp + 8]       = f2tff(O[nt][1] * inv0);
            Og[((i0 + 8) << 6) + dp]     = f2tff(O[nt][2] * inv1);
            Og[((i0 + 8) << 6) + dp + 8] = f2tff(O[nt][3] * inv1);
        }
    }
}

// ---------------------------------------------------------------------------
// Kernel 3: proj GEMM
// ---------------------------------------------------------------------------
__global__ __launch_bounds__(256, 2) void proj_mma_kernel(const float* __restrict__ bias,
                                                          float* __restrict__ out)
{
    extern __shared__ float smem[];
    float* As = smem;
    float* Bs = smem + 2 * TSZ;

    const int tid  = threadIdx.x;
    const int lane = tid & 31;
    const int warp = tid >> 5;
    const int gi = lane >> 2, gc = lane & 3;
    const int wm = (warp >> 2) * 64;
    const int wn = (warp & 3) * 32;
    const int m0 = blockIdx.y * 128, n0 = blockIdx.x * 128;

    float C[4][4][4] = {};

#define PROJ_LOAD(s, k0)                                                          \
    {                                                                             \
        int hh = (k0) >> 6, dbase = (k0) & 63;                                    \
        _Pragma("unroll")                                                         \
        for (int i = 0; i < 4; i++) {                                            \
            int f4 = i * 256 + tid;                                              \
            int row = f4 >> 3, col = (f4 & 7) << 2;                              \
            int m = m0 + row;                                                    \
            int b = m >> 11, t = m & 2047;                                       \
            cpa16(&As[(s)*TSZ + row * TS + col],                                 \
                  &g_att[(((size_t)((b << 4) + hh) << 11) + t) * HD + dbase + col]); \
            cpa16(&Bs[(s)*TSZ + row * TS + col],                                 \
                  &g_wprojT[(size_t)(n0 + row) * CC + (k0) + col]);              \
        }                                                                        \
        CP_COMMIT;                                                               \
    }

    PROJ_LOAD(0, 0);
    for (int it = 0; it < 32; it++) {
        const int s = it & 1;
        if (it + 1 < 32) { PROJ_LOAD(s ^ 1, (it + 1) * 32); CP_WAIT1; }
        else             { CP_WAIT0; }
        __syncthreads();
        const float* Asb = As + s * TSZ;
        const float* Bsb = Bs + s * TSZ;
        GEMM_COMPUTE(Asb, Bsb);
        __syncthreads();
    }

    #pragma unroll
    for (int tm = 0; tm < 4; tm++) {
        #pragma unroll
        for (int tn = 0; tn < 4; tn++) {
            #pragma unroll
            for (int e = 0; e < 4; e++) {
                int m = m0 + wm + tm * 16 + gi + ((e >= 2) ? 8 : 0);
                int n = n0 + wn + tn * 8 + 2 * gc + (e & 1);
                out[(size_t)m * CC + n] = C[tm][tn][e] + bias[n];
            }
        }
    }
}

// ---------------------------------------------------------------------------
extern "C" void kernel_launch(void* const* d_in, const int* in_sizes, int n_in,
                              void* d_out, int out_size)
{
    const float* x     = (const float*)d_in[0];
    const float* Wqkv  = (const float*)d_in[1];
    const float* bqkv  = (const float*)d_in[2];
    const float* Wproj = (const float*)d_in[3];
    const float* bproj = (const float*)d_in[4];
    float* out = (float*)d_out;

    const int GEMM_SMEM = 4 * TSZ * 4;                       // 73728 B
    const int ATTN_SMEM = (4 * KV_SZ + 128 * APAD) * 4;      // 104448 B
    cudaFuncSetAttribute(qkv_mma_kernel,
                         cudaFuncAttributeMaxDynamicSharedMemorySize, GEMM_SMEM);
    cudaFuncSetAttribute(proj_mma_kernel,
                         cudaFuncAttributeMaxDynamicSharedMemorySize, GEMM_SMEM);
    cudaFuncSetAttribute(attn_mma_kernel,
                         cudaFuncAttributeMaxDynamicSharedMemorySize, ATTN_SMEM);

    float* xt; float* wq; float* wp;
    cudaGetSymbolAddress((void**)&xt, g_xt);
    cudaGetSymbolAddress((void**)&wq, g_wqkvT);
    cudaGetSymbolAddress((void**)&wp, g_wprojT);

    perm_x_kernel<<<4096, 256>>>(x, xt);                                  // 4096x1024
    transpose_perm_kernel<<<dim3(96, 32), 256>>>(Wqkv, wq, 3 * CC);       // -> [3072][1024]
    transpose_perm_kernel<<<dim3(32, 32), 256>>>(Wproj, wp, CC);          // -> [1024][1024]

    qkv_mma_kernel<<<dim3(24, 32), 256, GEMM_SMEM>>>(bqkv);
    attn_mma_kernel<<<dim3(8, 32), 256, ATTN_SMEM>>>();
    proj_mma_kernel<<<dim3(8, 32), 256, GEMM_SMEM>>>(bproj, out);
}

// round 7
// speedup vs baseline: 1.1893x; 1.0332x over previous
#include <cuda_runtime.h>
#include <math.h>

#define BB 2
#define TT 2048
#define CC 1024
#define NH 16
#define HD 64
#define BH (BB*NH)

// scratch — all tf32-encoded, fragment-permuted layouts
__device__ float g_q[(size_t)BH * TT * HD];      // [bh][t][d_perm], pre-scaled 1/8
__device__ float g_k[(size_t)BH * TT * HD];      // [bh][t][d_perm]
__device__ float g_vt[(size_t)BH * HD * TT];     // [bh][d][t_perm]  (V transposed)
__device__ float g_att[(size_t)BH * TT * HD];    // [bh][t][d_perm]
__device__ float g_xt[(size_t)BB * TT * CC];     // [m][k_perm]
__device__ float g_wqkvT[(size_t)3 * CC * CC];   // [n][k_perm]
__device__ float g_wprojT[(size_t)CC * CC];      // [n][k_perm]

// perm within each 32-k chunk: perm(k) = (k%4)*8 + (k%32)/4
__device__ __forceinline__ int dperm64(int d) {
    return (d & 32) + ((d & 3) << 3) + ((d & 31) >> 2);
}

__device__ __forceinline__ unsigned f2tf(float f) {
    unsigned u;
    asm("cvt.rna.tf32.f32 %0, %1;" : "=r"(u) : "f"(f));
    return u;
}
__device__ __forceinline__ float f2tff(float f) { return __uint_as_float(f2tf(f)); }

__device__ __forceinline__ void mma8(float* c, float a0, float a1, float a2, float a3,
                                     float b0, float b1) {
    asm volatile(
        "mma.sync.aligned.m16n8k8.row.col.f32.tf32.tf32.f32 "
        "{%0,%1,%2,%3}, {%4,%5,%6,%7}, {%8,%9}, {%0,%1,%2,%3};"
        : "+f"(c[0]), "+f"(c[1]), "+f"(c[2]), "+f"(c[3])
        : "r"(__float_as_uint(a0)), "r"(__float_as_uint(a1)),
          "r"(__float_as_uint(a2)), "r"(__float_as_uint(a3)),
          "r"(__float_as_uint(b0)), "r"(__float_as_uint(b1)));
}

__device__ __forceinline__ void cpa16(float* smem_dst, const float* gptr) {
    unsigned s = (unsigned)__cvta_generic_to_shared(smem_dst);
    asm volatile("cp.async.cg.shared.global [%0], [%1], 16;" :: "r"(s), "l"(gptr));
}
#define CP_COMMIT asm volatile("cp.async.commit_group;")
#define CP_WAIT0  asm volatile("cp.async.wait_group 0;")

// ---------------------------------------------------------------------------
// pre-pass: x -> [m][k_perm] tf32
// ---------------------------------------------------------------------------
__global__ __launch_bounds__(256) void perm_x_kernel(const float* __restrict__ in,
                                                     float* __restrict__ out)
{
    size_t o = ((size_t)blockIdx.x * 256 + threadIdx.x) * 4;
    size_t row = o >> 10;
    int col = (int)(o & 1023);
    int chunk = col & ~31, p = col & 31;
    float r[4];
    #pragma unroll
    for (int j = 0; j < 4; j++) {
        int pj = p + j;
        int k = ((pj & 7) << 2) + (pj >> 3);
        r[j] = f2tff(in[(row << 10) + chunk + k]);
    }
    *(float4*)&out[o] = make_float4(r[0], r[1], r[2], r[3]);
}

// pre-pass: W[K=1024][N] -> out[N][1024 k_perm] tf32 (tiled transpose)
__global__ __launch_bounds__(256) void transpose_perm_kernel(const float* __restrict__ in,
                                                             float* __restrict__ out,
                                                             int N)
{
    __shared__ float t[32][33];
    const int k0 = blockIdx.y << 5, n0 = blockIdx.x << 5;
    const int tx = threadIdx.x & 31, ty = threadIdx.x >> 5;
    #pragma unroll
    for (int i = 0; i < 4; i++)
        t[ty + 8 * i][tx] = f2tff(in[(size_t)(k0 + ty + 8 * i) * N + n0 + tx]);
    __syncthreads();
    const int pp = ((tx & 3) << 3) + (tx >> 2);
    #pragma unroll
    for (int i = 0; i < 4; i++)
        out[(size_t)(n0 + ty + 8 * i) * 1024 + k0 + pp] = t[tx][ty + 8 * i];
}

// ---------------------------------------------------------------------------
// GEMM microkernel. Block tile 128x128, BK=32, 2-stage, ONE sync per iter.
// A smem [128 m][36], B smem [128 n][36], both k-permuted.
// ---------------------------------------------------------------------------
#define TS 36
#define TSZ (128*TS)

#define GEMM_COMPUTE(Asb, Bsb)                                                   \
    _Pragma("unroll")                                                            \
    for (int kp = 0; kp < 2; kp++) {                                             \
        float4 alo[4], ahi[4], bf[4];                                            \
        _Pragma("unroll")                                                        \
        for (int tm = 0; tm < 4; tm++) {                                         \
            int r = wm + tm * 16 + gi;                                           \
            alo[tm] = *(const float4*)&(Asb)[r * TS + gc * 8 + kp * 4];           \
            ahi[tm] = *(const float4*)&(Asb)[(r + 8) * TS + gc * 8 + kp * 4];     \
        }                                                                        \
        _Pragma("unroll")                                                        \
        for (int tn = 0; tn < 4; tn++) {                                         \
            int n = wn + tn * 8 + gi;                                            \
            bf[tn] = *(const float4*)&(Bsb)[n * TS + gc * 8 + kp * 4];            \
        }                                                                        \
        _Pragma("unroll")                                                        \
        for (int tm = 0; tm < 4; tm++)                                           \
            _Pragma("unroll")                                                    \
            for (int tn = 0; tn < 4; tn++) {                                     \
                mma8(C[tm][tn], alo[tm].x, ahi[tm].x, alo[tm].y, ahi[tm].y,      \
                     bf[tn].x, bf[tn].y);                                        \
                mma8(C[tm][tn], alo[tm].z, ahi[tm].z, alo[tm].w, ahi[tm].w,      \
                     bf[tn].z, bf[tn].w);                                        \
            }                                                                    \
    }

// ---------------------------------------------------------------------------
// Kernel 1: QKV GEMM
// ---------------------------------------------------------------------------
__global__ __launch_bounds__(256, 2) void qkv_mma_kernel(const float* __restrict__ bias)
{
    extern __shared__ float smem[];
    float* As = smem;              // [2][128][36]
    float* Bs = smem + 2 * TSZ;

    const int tid  = threadIdx.x;
    const int lane = tid & 31;
    const int warp = tid >> 5;
    const int gi = lane >> 2, gc = lane & 3;
    const int wm = (warp >> 2) * 64;
    const int wn = (warp & 3) * 32;
    const int m0 = blockIdx.y * 128, n0 = blockIdx.x * 128;

    // per-thread load geometry: rows r0+32i, fixed col c0
    const int r0 = tid >> 3, c0 = (tid & 7) << 2;
    const float* ga = g_xt    + (size_t)(m0 + r0) * CC + c0;
    const float* gb = g_wqkvT + (size_t)(n0 + r0) * CC + c0;
    float* sa = As + r0 * TS + c0;
    float* sb = Bs + r0 * TS + c0;

    float C[4][4][4] = {};

    // prologue: stage 0
    #pragma unroll
    for (int i = 0; i < 4; i++) {
        cpa16(sa + i * 32 * TS, ga + (size_t)i * 32 * CC);
        cpa16(sb + i * 32 * TS, gb + (size_t)i * 32 * CC);
    }
    CP_COMMIT;

    for (int it = 0; it < 32; it++) {
        const int s = it & 1;
        CP_WAIT0;
        __syncthreads();
        if (it + 1 < 32) {
            const float* gan = ga + (it + 1) * 32;
            const float* gbn = gb + (it + 1) * 32;
            float* san = sa + (s ^ 1) * TSZ;
            float* sbn = sb + (s ^ 1) * TSZ;
            #pragma unroll
            for (int i = 0; i < 4; i++) {
                cpa16(san + i * 32 * TS, gan + (size_t)i * 32 * CC);
                cpa16(sbn + i * 32 * TS, gbn + (size_t)i * 32 * CC);
            }
            CP_COMMIT;
        }
        const float* Asb = As + s * TSZ;
        const float* Bsb = Bs + s * TSZ;
        GEMM_COMPUTE(Asb, Bsb);
    }

    #pragma unroll
    for (int tm = 0; tm < 4; tm++) {
        #pragma unroll
        for (int tn = 0; tn < 4; tn++) {
            #pragma unroll
            for (int e = 0; e < 4; e++) {
                int m = m0 + wm + tm * 16 + gi + ((e >= 2) ? 8 : 0);
                int n = n0 + wn + tn * 8 + 2 * gc + (e & 1);
                float v = C[tm][tn][e] + bias[n];
                int b = m >> 11, t = m & 2047;
                int h = n / 192;
                int r = n - h * 192;
                int d = r & 63;
                int bh = (b << 4) + h;
                if (r < 64) {
                    g_q[((size_t)bh << 17) + ((size_t)t << 6) + dperm64(d)] =
                        f2tff(v * 0.125f);
                } else if (r < 128) {
                    g_k[((size_t)bh << 17) + ((size_t)t << 6) + dperm64(d)] = f2tff(v);
                } else {
                    int tp = (t & ~31) + ((t & 3) << 3) + ((t & 31) >> 2);
                    g_vt[((size_t)(bh * 64 + d) << 11) + tp] = f2tff(v);
                }
            }
        }
    }
}

// ---------------------------------------------------------------------------
// Kernel 2: causal flash attention. 256 thr, 128-query tile, 64-key tiles,
// ONE syncthreads per key tile. Block x handles qt = x and 15-x.
// ---------------------------------------------------------------------------
#define APAD 68
#define KV_SZ (64*APAD)

__global__ __launch_bounds__(256, 2) void attn_mma_kernel()
{
    extern __shared__ float sm[];
    float* sK  = sm;                 // [2][64 key][68 dim_perm]
    float* sVt = sm + 2 * KV_SZ;     // [2][64 dim][68 key_perm]
    float* sP  = sm + 4 * KV_SZ;     // [128][68]  Q then P

    const int bh = blockIdx.y;
    const int tid = threadIdx.x;
    const int lane = tid & 31;
    const int warp = tid >> 5;
    const int gi = lane >> 2, gc = lane & 3;
    const int i0 = warp * 16 + gi;

    const float* Kg = g_k + ((size_t)bh << 17);
    const float* Vtg = g_vt + ((size_t)bh << 17);

#define KV_LOAD(s, kt)                                                        \
    {                                                                         \
        _Pragma("unroll")                                                     \
        for (int i = 0; i < 4; i++) {                                         \
            int f4 = i * 256 + tid;                                           \
            int r = f4 >> 4, c = (f4 & 15) << 2;                              \
            cpa16(&sK[((s)*64 + r) * APAD + c],                               \
                  &Kg[(size_t)(((kt) << 6) + r) * HD + c]);                   \
            cpa16(&sVt[((s)*64 + r) * APAD + c],                              \
                  &Vtg[((size_t)r << 11) + ((kt) << 6) + c]);                 \
        }                                                                     \
        CP_COMMIT;                                                            \
    }

    for (int pi = 0; pi < 2; pi++) {
        const int qt = pi ? (15 - (int)blockIdx.x) : (int)blockIdx.x;
        const int ktmax = 2 * qt + 1;
        const float* Qg = g_q + ((size_t)bh << 17) + ((size_t)qt << 13);

        __syncthreads();   // all warps done with previous pi's sP/sK/sVt
        // stage Q
        #pragma unroll
        for (int i = 0; i < 8; i++) {
            int f4 = i * 256 + tid;
            int r = f4 >> 4, c = (f4 & 15) << 2;
            cpa16(&sP[r * APAD + c], &Qg[(r << 6) + c]);
        }
        CP_COMMIT;
        KV_LOAD(0, 0);

        float4 qlo[4], qhi[4];    // [c*2+h]
        float O[8][4] = {};
        float m0r = -1e30f, m1r = -1e30f, l0r = 0.f, l1r = 0.f;

        for (int kt = 0; kt <= ktmax; kt++) {
            const int s = kt & 1;
            CP_WAIT0;
            __syncthreads();   // stage-s data ready AND all warps done reading s^1

            if (kt < ktmax) KV_LOAD(s ^ 1, kt + 1);

            if (kt == 0) {
                #pragma unroll
                for (int c = 0; c < 2; c++)
                    #pragma unroll
                    for (int h = 0; h < 2; h++) {
                        qlo[c * 2 + h] = *(const float4*)&sP[i0 * APAD + c * 32 + gc * 8 + h * 4];
                        qhi[c * 2 + h] = *(const float4*)&sP[(i0 + 8) * APAD + c * 32 + gc * 8 + h * 4];
                    }
            }

            const bool active = (kt * 64 <= qt * 128 + warp * 16 + 15);
            if (active) {
                const float* sKb  = sK + s * KV_SZ;
                const float* sVtb = sVt + s * KV_SZ;

                // ---- S = Q @ K^T ----
                float S[8][4] = {};
                #pragma unroll
                for (int c = 0; c < 2; c++)
                    #pragma unroll
                    for (int h = 0; h < 2; h++) {
                        float4 qL = qlo[c * 2 + h], qH = qhi[c * 2 + h];
                        #pragma unroll
                        for (int nt = 0; nt < 8; nt++) {
                            int n = nt * 8 + gi;
                            float4 kb = *(const float4*)&sKb[n * APAD + c * 32 + gc * 8 + h * 4];
                            mma8(S[nt], qL.x, qH.x, qL.y, qH.y, kb.x, kb.y);
                            mma8(S[nt], qL.z, qH.z, qL.w, qH.w, kb.z, kb.w);
                        }
                    }

                if (kt >= 2 * qt) {
                    int ig0 = qt * 128 + i0;
                    #pragma unroll
                    for (int nt = 0; nt < 8; nt++) {
                        int j0 = kt * 64 + nt * 8 + 2 * gc;
                        if (j0 > ig0)         S[nt][0] = -1e30f;
                        if (j0 + 1 > ig0)     S[nt][1] = -1e30f;
                        if (j0 > ig0 + 8)     S[nt][2] = -1e30f;
                        if (j0 + 1 > ig0 + 8) S[nt][3] = -1e30f;
                    }
                }

                float mx0 = -1e30f, mx1 = -1e30f;
                #pragma unroll
                for (int nt = 0; nt < 8; nt++) {
                    mx0 = fmaxf(mx0, fmaxf(S[nt][0], S[nt][1]));
                    mx1 = fmaxf(mx1, fmaxf(S[nt][2], S[nt][3]));
                }
                mx0 = fmaxf(mx0, __shfl_xor_sync(0xffffffffu, mx0, 1));
                mx0 = fmaxf(mx0, __shfl_xor_sync(0xffffffffu, mx0, 2));
                mx1 = fmaxf(mx1, __shfl_xor_sync(0xffffffffu, mx1, 1));
                mx1 = fmaxf(mx1, __shfl_xor_sync(0xffffffffu, mx1, 2));

                float mn0 = fmaxf(m0r, mx0), mn1 = fmaxf(m1r, mx1);
                float c0 = __expf(m0r - mn0), c1 = __expf(m1r - mn1);

                float ls0 = 0.f, ls1 = 0.f;
                #pragma unroll
                for (int nt = 0; nt < 8; nt++) {
                    float p0 = __expf(S[nt][0] - mn0);
                    float p1 = __expf(S[nt][1] - mn0);
                    float p2 = __expf(S[nt][2] - mn1);
                    float p3 = __expf(S[nt][3] - mn1);
                    ls0 += p0 + p1;
                    ls1 += p2 + p3;
                    // key-permuted P store
                    int chunk = (nt >> 2) << 5;
                    int pos0 = chunk + (((2 * gc) & 3) << 3) + 2 * (nt & 3) + (gc >> 1);
                    sP[i0 * APAD + pos0]           = f2tff(p0);
                    sP[i0 * APAD + pos0 + 8]       = f2tff(p1);
                    sP[(i0 + 8) * APAD + pos0]     = f2tff(p2);
                    sP[(i0 + 8) * APAD + pos0 + 8] = f2tff(p3);
                }
                ls0 += __shfl_xor_sync(0xffffffffu, ls0, 1);
                ls0 += __shfl_xor_sync(0xffffffffu, ls0, 2);
                ls1 += __shfl_xor_sync(0xffffffffu, ls1, 1);
                ls1 += __shfl_xor_sync(0xffffffffu, ls1, 2);
                l0r = l0r * c0 + ls0;
                l1r = l1r * c1 + ls1;
                m0r = mn0; m1r = mn1;

                #pragma unroll
                for (int nt = 0; nt < 8; nt++) {
                    O[nt][0] *= c0; O[nt][1] *= c0;
                    O[nt][2] *= c1; O[nt][3] *= c1;
                }

                __syncwarp();  // P produced & consumed within this warp

                // ---- O += P @ V  (B = V^T, key-permuted) ----
                #pragma unroll
                for (int c = 0; c < 2; c++)
                    #pragma unroll
                    for (int h = 0; h < 2; h++) {
                        float4 pL = *(const float4*)&sP[i0 * APAD + c * 32 + gc * 8 + h * 4];
                        float4 pH = *(const float4*)&sP[(i0 + 8) * APAD + c * 32 + gc * 8 + h * 4];
                        #pragma unroll
                        for (int nt = 0; nt < 8; nt++) {
                            int n = nt * 8 + gi;
                            float4 vb = *(const float4*)&sVtb[n * APAD + c * 32 + gc * 8 + h * 4];
                            mma8(O[nt], pL.x, pH.x, pL.y, pH.y, vb.x, vb.y);
                            mma8(O[nt], pL.z, pH.z, pL.w, pH.w, vb.z, vb.w);
                        }
                    }
                __syncwarp();
            }
        }

        float inv0 = 1.f / l0r, inv1 = 1.f / l1r;
        float* Og = g_att + ((size_t)bh << 17) + ((size_t)qt << 13);
        #pragma unroll
        for (int nt = 0; nt < 8; nt++) {
            int d0 = nt * 8 + 2 * gc;
            int dp = dperm64(d0);
            Og[(i0 << 6) + dp]           = f2tff(O[nt][0] * inv0);
            Og[(i0 << 6) + dp + 8]       = f2tff(O[nt][1] * inv0);
            Og[((i0 + 8) << 6) + dp]     = f2tff(O[nt][2] * inv1);
            Og[((i0 + 8) << 6) + dp + 8] = f2tff(O[nt][3] * inv1);
        }
    }
}

// ---------------------------------------------------------------------------
// Kernel 3: proj GEMM, one sync per iter
// ---------------------------------------------------------------------------
__global__ __launch_bounds__(256, 2) void proj_mma_kernel(const float* __restrict__ bias,
                                                          float* __restrict__ out)
{
    extern __shared__ float smem[];
    float* As = smem;
    float* Bs = smem + 2 * TSZ;

    const int tid  = threadIdx.x;
    const int lane = tid & 31;
    const int warp = tid >> 5;
    const int gi = lane >> 2, gc = lane & 3;
    const int wm = (warp >> 2) * 64;
    const int wn = (warp & 3) * 32;
    const int m0 = blockIdx.y * 128, n0 = blockIdx.x * 128;

    const int r0 = tid >> 3, c0 = (tid & 7) << 2;
    const int m = m0 + r0;
    const int bb = m >> 11, tt = m & 2047;
    const float* gaBase = g_att + (((size_t)(bb << 4) << 11) + tt) * HD + c0;  // + h*2^17 + dbase
    const float* gb = g_wprojT + (size_t)(n0 + r0) * CC + c0;
    float* sa = As + r0 * TS + c0;
    float* sb = Bs + r0 * TS + c0;

    float C[4][4][4] = {};

#define PROJ_LOAD(sdst, k0)                                                       \
    {                                                                             \
        int hh = (k0) >> 6, dbase = (k0) & 63;                                    \
        const float* gan = gaBase + (((size_t)hh) << 17) + dbase;                 \
        const float* gbn = gb + (k0);                                             \
        _Pragma("unroll")                                                         \
        for (int i = 0; i < 4; i++) {                                             \
            cpa16(sa + (sdst) * TSZ + i * 32 * TS, gan + (((size_t)i * 32) >> 7 << 24)); \
            cpa16(sb + (sdst) * TSZ + i * 32 * TS, gbn + (size_t)i * 32 * CC);    \
        }                                                                         \
        CP_COMMIT;                                                                \
    }

    // NOTE: A rows advance in m (token) dim: row = r0 + 32i -> m += 32i.
    // m crosses b/t only via t (t = m & 2047); within a 128-row tile t advances by 32i
    // except possibly wrapping b at m=2048. Handle precisely instead of the macro above.
#undef PROJ_LOAD
#define PROJ_LOAD(sdst, k0)                                                       \
    {                                                                             \
        int hh = (k0) >> 6, dbase = (k0) & 63;                                    \
        _Pragma("unroll")                                                         \
        for (int i = 0; i < 4; i++) {                                             \
            int mm = m0 + r0 + 32 * i;                                            \
            int b2 = mm >> 11, t2 = mm & 2047;                                    \
            cpa16(sa + (sdst) * TSZ + i * 32 * TS,                                \
                  &g_att[(((size_t)((b2 << 4) + hh) << 11) + t2) * HD + dbase + c0]); \
            cpa16(sb + (sdst) * TSZ + i * 32 * TS, gb + (k0) + (size_t)i * 32 * CC); \
        }                                                                         \
        CP_COMMIT;                                                                \
    }

    PROJ_LOAD(0, 0);
    for (int it = 0; it < 32; it++) {
        const int s = it & 1;
        CP_WAIT0;
        __syncthreads();
        if (it + 1 < 32) PROJ_LOAD(s ^ 1, (it + 1) * 32);
        const float* Asb = As + s * TSZ;
        const float* Bsb = Bs + s * TSZ;
        GEMM_COMPUTE(Asb, Bsb);
    }

    #pragma unroll
    for (int tm = 0; tm < 4; tm++) {
        #pragma unroll
        for (int tn = 0; tn < 4; tn++) {
            #pragma unroll
            for (int e = 0; e < 4; e++) {
                int mm = m0 + wm + tm * 16 + gi + ((e >= 2) ? 8 : 0);
                int n = n0 + wn + tn * 8 + 2 * gc + (e & 1);
                out[(size_t)mm * CC + n] = C[tm][tn][e] + bias[n];
            }
        }
    }
}

// ---------------------------------------------------------------------------
extern "C" void kernel_launch(void* const* d_in, const int* in_sizes, int n_in,
                              void* d_out, int out_size)
{
    const float* x     = (const float*)d_in[0];
    const float* Wqkv  = (const float*)d_in[1];
    const float* bqkv  = (const float*)d_in[2];
    const float* Wproj = (const float*)d_in[3];
    const float* bproj = (const float*)d_in[4];
    float* out = (float*)d_out;

    const int GEMM_SMEM = 4 * TSZ * 4;                       // 73728 B
    const int ATTN_SMEM = (4 * KV_SZ + 128 * APAD) * 4;      // 104448 B
    cudaFuncSetAttribute(qkv_mma_kernel,
                         cudaFuncAttributeMaxDynamicSharedMemorySize, GEMM_SMEM);
    cudaFuncSetAttribute(proj_mma_kernel,
                         cudaFuncAttributeMaxDynamicSharedMemorySize, GEMM_SMEM);
    cudaFuncSetAttribute(attn_mma_kernel,
                         cudaFuncAttributeMaxDynamicSharedMemorySize, ATTN_SMEM);

    float* xt; float* wq; float* wp;
    cudaGetSymbolAddress((void**)&xt, g_xt);
    cudaGetSymbolAddress((void**)&wq, g_wqkvT);
    cudaGetSymbolAddress((void**)&wp, g_wprojT);

    perm_x_kernel<<<4096, 256>>>(x, xt);                                  // 4096x1024
    transpose_perm_kernel<<<dim3(96, 32), 256>>>(Wqkv, wq, 3 * CC);       // -> [3072][1024]
    transpose_perm_kernel<<<dim3(32, 32), 256>>>(Wproj, wp, CC);          // -> [1024][1024]

    qkv_mma_kernel<<<dim3(24, 32), 256, GEMM_SMEM>>>(bqkv);
    attn_mma_kernel<<<dim3(8, 32), 256, ATTN_SMEM>>>();
    proj_mma_kernel<<<dim3(8, 32), 256, GEMM_SMEM>>>(bproj, out);
}

// round 10
// speedup vs baseline: 1.7259x; 1.4512x over previous
#include <cuda_runtime.h>
#include <cuda_fp16.h>
#include <math.h>
#include <stdint.h>

#define BB 2
#define TT 2048
#define CC 1024
#define NH 16
#define HD 64
#define BH (BB*NH)

// scratch — all fp16, fragment-permuted within 32-element k-chunks
__device__ __half g_q[(size_t)BH * TT * HD];      // [bh][t][d_pos], pre-scaled 1/8
__device__ __half g_k[(size_t)BH * TT * HD];      // [bh][t][d_pos]
__device__ __half g_vt[(size_t)BH * HD * TT];     // [bh][d][t_pos]
__device__ __half g_att[(size_t)BH * TT * HD];    // [bh][t][d_pos]
__device__ __half g_xt[(size_t)BB * TT * CC];     // [m][k_pos]
__device__ __half g_wqkvT[(size_t)3 * CC * CC];   // [n][k_pos]
__device__ __half g_wprojT[(size_t)CC * CC];      // [n][k_pos]

// perm within 32-chunk: k = 16h+8b+2g+l -> pos = g*8 + 4h + 2b + l
__device__ __forceinline__ int hpos(int k) {
    return (k & ~31) + (((k >> 1) & 3) << 3) + (((k >> 4) & 1) << 2)
         + (((k >> 3) & 1) << 1) + (k & 1);
}

__device__ __forceinline__ uint32_t h2u(__half2 h) { return *(uint32_t*)&h; }

__device__ __forceinline__ void mma16(float* c,
                                      uint32_t a0, uint32_t a1, uint32_t a2, uint32_t a3,
                                      uint32_t b0, uint32_t b1) {
    asm volatile(
        "mma.sync.aligned.m16n8k16.row.col.f32.f16.f16.f32 "
        "{%0,%1,%2,%3}, {%4,%5,%6,%7}, {%8,%9}, {%0,%1,%2,%3};"
        : "+f"(c[0]), "+f"(c[1]), "+f"(c[2]), "+f"(c[3])
        : "r"(a0), "r"(a1), "r"(a2), "r"(a3), "r"(b0), "r"(b1));
}

__device__ __forceinline__ void cpa16(void* smem_dst, const void* gptr) {
    unsigned s = (unsigned)__cvta_generic_to_shared(smem_dst);
    asm volatile("cp.async.cg.shared.global [%0], [%1], 16;" :: "r"(s), "l"(gptr));
}
#define CP_COMMIT asm volatile("cp.async.commit_group;")
#define CP_WAIT0  asm volatile("cp.async.wait_group 0;")

// ---------------------------------------------------------------------------
// pre-pass: x (fp32 [m][1024]) -> g_xt fp16 [m][k_pos]
// ---------------------------------------------------------------------------
__global__ __launch_bounds__(256) void cvt_x_kernel(const float* __restrict__ in,
                                                    __half* __restrict__ out)
{
    int gid = blockIdx.x * 256 + threadIdx.x;     // unit of 8 halves
    int row = gid >> 7;
    int uc = gid & 127;
    int cb = (uc >> 2) << 5;                      // chunk base k
    int g = uc & 3;
    const float* src = in + (size_t)row * CC + cb + 2 * g;
    float2 v0 = *(const float2*)(src);
    float2 v1 = *(const float2*)(src + 8);
    float2 v2 = *(const float2*)(src + 16);
    float2 v3 = *(const float2*)(src + 24);
    uint4 o;
    o.x = h2u(__floats2half2_rn(v0.x, v0.y));
    o.y = h2u(__floats2half2_rn(v1.x, v1.y));
    o.z = h2u(__floats2half2_rn(v2.x, v2.y));
    o.w = h2u(__floats2half2_rn(v3.x, v3.y));
    *(uint4*)(out + (size_t)row * CC + cb + g * 8) = o;
}

// pre-pass: W fp32 [K=1024][N] -> out fp16 [N][k_pos] (tiled transpose)
__global__ __launch_bounds__(128) void transpose_h_kernel(const float* __restrict__ in,
                                                          __half* __restrict__ out,
                                                          int N)
{
    __shared__ float t[32][33];
    const int k0 = blockIdx.y << 5, n0 = blockIdx.x << 5;
    const int tid = threadIdx.x;
    #pragma unroll
    for (int i = 0; i < 8; i++) {
        int idx = i * 128 + tid;
        int r = idx >> 5, c = idx & 31;
        t[r][c] = in[(size_t)(k0 + r) * N + n0 + c];
    }
    __syncthreads();
    int nl = tid >> 2, g = tid & 3;
    uint4 o;
    o.x = h2u(__floats2half2_rn(t[2*g][nl],      t[2*g+1][nl]));
    o.y = h2u(__floats2half2_rn(t[2*g+8][nl],    t[2*g+9][nl]));
    o.z = h2u(__floats2half2_rn(t[2*g+16][nl],   t[2*g+17][nl]));
    o.w = h2u(__floats2half2_rn(t[2*g+24][nl],   t[2*g+25][nl]));
    *(uint4*)(out + (size_t)(n0 + nl) * 1024 + k0 + g * 8) = o;
}

// ---------------------------------------------------------------------------
// fp16 GEMM microkernel. Block tile 128x128, BK=64, 2-stage, one sync/iter.
// smem rows: 64 halves + pad -> 144 B rows (conflict-free lds.128).
// ---------------------------------------------------------------------------
#define HROW 144
#define HSTG (128*HROW)
#define GEMM_SMEM (4*HSTG)      // 73728 B

#define GEMM_COMPUTE16(Asb, Bsb)                                                 \
    _Pragma("unroll")                                                            \
    for (int kc = 0; kc < 2; kc++) {                                             \
        uint4 alo[4], ahi[4], bf[4];                                             \
        _Pragma("unroll")                                                        \
        for (int tm = 0; tm < 4; tm++) {                                         \
            int r = wm + tm * 16 + gi;                                           \
            alo[tm] = *(const uint4*)((Asb) + r * HROW + kc * 64 + gc * 16);     \
            ahi[tm] = *(const uint4*)((Asb) + (r + 8) * HROW + kc * 64 + gc * 16); \
        }                                                                        \
        _Pragma("unroll")                                                        \
        for (int tn = 0; tn < 4; tn++) {                                         \
            int n = wn + tn * 8 + gi;                                            \
            bf[tn] = *(const uint4*)((Bsb) + n * HROW + kc * 64 + gc * 16);      \
        }                                                                        \
        _Pragma("unroll")                                                        \
        for (int tm = 0; tm < 4; tm++)                                           \
            _Pragma("unroll")                                                    \
            for (int tn = 0; tn < 4; tn++) {                                     \
                mma16(C[tm][tn], alo[tm].x, ahi[tm].x, alo[tm].y, ahi[tm].y,     \
                      bf[tn].x, bf[tn].y);                                       \
                mma16(C[tm][tn], alo[tm].z, ahi[tm].z, alo[tm].w, ahi[tm].w,     \
                      bf[tn].z, bf[tn].w);                                       \
            }                                                                    \
    }

// ---------------------------------------------------------------------------
// Kernel 1: QKV GEMM (fp16)
// ---------------------------------------------------------------------------
__global__ __launch_bounds__(256, 2) void qkv_mma_kernel(const float* __restrict__ bias)
{
    extern __shared__ char smc[];
    char* sA = smc;                 // [2][128][144B]
    char* sB = smc + 2 * HSTG;

    const int tid  = threadIdx.x;
    const int lane = tid & 31;
    const int warp = tid >> 5;
    const int gi = lane >> 2, gc = lane & 3;
    const int wm = (warp >> 2) * 64;
    const int wn = (warp & 3) * 32;
    const int m0 = blockIdx.y * 128, n0 = blockIdx.x * 128;

    const int r0 = tid >> 1, u0 = (tid & 1) * 4;     // 2 threads/row, 4 units each
    const __half* gA = g_xt    + (size_t)(m0 + r0) * CC + u0 * 8;
    const __half* gB = g_wqkvT + (size_t)(n0 + r0) * CC + u0 * 8;
    char* da = sA + r0 * HROW + u0 * 16;
    char* db = sB + r0 * HROW + u0 * 16;

    float C[4][4][4] = {};

#define QLOAD(s, kh)                                                   \
    {                                                                  \
        _Pragma("unroll")                                              \
        for (int j = 0; j < 4; j++) {                                  \
            cpa16(da + (s) * HSTG + j * 16, gA + (kh) + j * 8);        \
            cpa16(db + (s) * HSTG + j * 16, gB + (kh) + j * 8);        \
        }                                                              \
        CP_COMMIT;                                                     \
    }

    QLOAD(0, 0);
    for (int it = 0; it < 16; it++) {
        const int s = it & 1;
        CP_WAIT0;
        __syncthreads();
        if (it + 1 < 16) QLOAD(s ^ 1, (it + 1) * 64);
        const char* Asb = sA + s * HSTG;
        const char* Bsb = sB + s * HSTG;
        GEMM_COMPUTE16(Asb, Bsb);
    }

    // epilogue: bias, scatter fp16 into q/k/vt with baked perms
    #pragma unroll
    for (int tm = 0; tm < 4; tm++) {
        #pragma unroll
        for (int tn = 0; tn < 4; tn++) {
            #pragma unroll
            for (int half_ = 0; half_ < 2; half_++) {    // rows gi / gi+8
                int m = m0 + wm + tm * 16 + gi + half_ * 8;
                int n = n0 + wn + tn * 8 + 2 * gc;       // even; pair (n, n+1)
                float v0 = C[tm][tn][half_ * 2 + 0] + bias[n];
                float v1 = C[tm][tn][half_ * 2 + 1] + bias[n + 1];
                int b = m >> 11, t = m & 2047;
                int h = n / 192;
                int r = n - h * 192;
                int d = r & 63;                           // even
                int bh = (b << 4) + h;
                if (r < 64) {
                    __half2 hv = __floats2half2_rn(v0 * 0.125f, v1 * 0.125f);
                    *(__half2*)(g_q + ((size_t)bh << 17) + ((size_t)t << 6) + hpos(d)) = hv;
                } else if (r < 128) {
                    __half2 hv = __floats2half2_rn(v0, v1);
                    *(__half2*)(g_k + ((size_t)bh << 17) + ((size_t)t << 6) + hpos(d)) = hv;
                } else {
                    int tp = hpos(t);
                    g_vt[((size_t)(bh * 64 + d)     << 11) + tp] = __float2half_rn(v0);
                    g_vt[((size_t)(bh * 64 + d + 1) << 11) + tp] = __float2half_rn(v1);
                }
            }
        }
    }
}

// ---------------------------------------------------------------------------
// Kernel 2: causal flash attention (fp16). 256 thr, 128-query tile,
// 64-key tiles, P kept in registers (no smem round-trip).
// ---------------------------------------------------------------------------
#define KVROW 144
#define KVBUF (64*KVROW)         // 9216 B
#define ATTN_SMEM (4*KVBUF)      // 36864 B

__global__ __launch_bounds__(256, 2) void attn_mma_kernel()
{
    extern __shared__ char smc[];
    char* sK  = smc;                   // [2][64 key][144B dim]
    char* sVt = smc + 2 * KVBUF;       // [2][64 dim][144B key]

    const int bh = blockIdx.y;
    const int tid = threadIdx.x;
    const int lane = tid & 31;
    const int warp = tid >> 5;
    const int gi = lane >> 2, gc = lane & 3;
    const int i0 = warp * 16 + gi;

    const __half* Kg  = g_k  + ((size_t)bh << 17);
    const __half* Vtg = g_vt + ((size_t)bh << 17);

    // FIX (R9 NaN): each 64x64 fp16 tile = 4096 halves = 512 16B units.
    // 256 threads -> 2 units per tensor per thread: bytes uu*32 + {0,16}.
    const int rr = tid >> 2, uu = tid & 3;
#define KV_LOAD(s, kt)                                                        \
    {                                                                         \
        cpa16(sK + (s) * KVBUF + rr * KVROW + uu * 32,                        \
              Kg + (size_t)(((kt) << 6) + rr) * HD + uu * 16);                \
        cpa16(sK + (s) * KVBUF + rr * KVROW + uu * 32 + 16,                   \
              Kg + (size_t)(((kt) << 6) + rr) * HD + uu * 16 + 8);            \
        cpa16(sVt + (s) * KVBUF + rr * KVROW + uu * 32,                       \
              Vtg + ((size_t)rr << 11) + ((kt) << 6) + uu * 16);              \
        cpa16(sVt + (s) * KVBUF + rr * KVROW + uu * 32 + 16,                  \
              Vtg + ((size_t)rr << 11) + ((kt) << 6) + uu * 16 + 8);          \
        CP_COMMIT;                                                            \
    }

    for (int pi = 0; pi < 2; pi++) {
        const int qt = pi ? (15 - (int)blockIdx.x) : (int)blockIdx.x;
        const int ktmax = 2 * qt + 1;
        const __half* Qg = g_q + ((size_t)bh << 17) + ((size_t)qt << 13);

        __syncthreads();   // all warps done with previous pi's buffers
        KV_LOAD(0, 0);

        // Q fragments straight from gmem (read once per pi)
        uint4 qa[2], qb[2];
        #pragma unroll
        for (int qc = 0; qc < 2; qc++) {
            qa[qc] = *(const uint4*)(Qg + i0 * 64 + qc * 32 + gc * 8);
            qb[qc] = *(const uint4*)(Qg + (i0 + 8) * 64 + qc * 32 + gc * 8);
        }

        float O[8][4] = {};
        float m0r = -1e30f, m1r = -1e30f, l0r = 0.f, l1r = 0.f;

        for (int kt = 0; kt <= ktmax; kt++) {
            const int s = kt & 1;
            CP_WAIT0;
            __syncthreads();
            if (kt < ktmax) KV_LOAD(s ^ 1, kt + 1);

            const bool active = (kt * 64 <= qt * 128 + warp * 16 + 15);
            if (active) {
                const char* sKb  = sK + s * KVBUF;
                const char* sVtb = sVt + s * KVBUF;

                // ---- S = Q @ K^T ----
                float S[8][4] = {};
                #pragma unroll
                for (int qc = 0; qc < 2; qc++) {
                    #pragma unroll
                    for (int nt = 0; nt < 8; nt++) {
                        int n = nt * 8 + gi;
                        uint4 kb = *(const uint4*)(sKb + n * KVROW + qc * 64 + gc * 16);
                        mma16(S[nt], qa[qc].x, qb[qc].x, qa[qc].y, qb[qc].y, kb.x, kb.y);
                        mma16(S[nt], qa[qc].z, qb[qc].z, qa[qc].w, qb[qc].w, kb.z, kb.w);
                    }
                }

                if (kt >= 2 * qt) {   // diagonal region: causal mask
                    int ig0 = qt * 128 + i0;
                    #pragma unroll
                    for (int nt = 0; nt < 8; nt++) {
                        int j0 = kt * 64 + nt * 8 + 2 * gc;
                        if (j0 > ig0)         S[nt][0] = -1e30f;
                        if (j0 + 1 > ig0)     S[nt][1] = -1e30f;
                        if (j0 > ig0 + 8)     S[nt][2] = -1e30f;
                        if (j0 + 1 > ig0 + 8) S[nt][3] = -1e30f;
                    }
                }

                // ---- online softmax, P -> registers (fp16 pairs) ----
                float mx0 = -1e30f, mx1 = -1e30f;
                #pragma unroll
                for (int nt = 0; nt < 8; nt++) {
                    mx0 = fmaxf(mx0, fmaxf(S[nt][0], S[nt][1]));
                    mx1 = fmaxf(mx1, fmaxf(S[nt][2], S[nt][3]));
                }
                mx0 = fmaxf(mx0, __shfl_xor_sync(0xffffffffu, mx0, 1));
                mx0 = fmaxf(mx0, __shfl_xor_sync(0xffffffffu, mx0, 2));
                mx1 = fmaxf(mx1, __shfl_xor_sync(0xffffffffu, mx1, 1));
                mx1 = fmaxf(mx1, __shfl_xor_sync(0xffffffffu, mx1, 2));

                float mn0 = fmaxf(m0r, mx0), mn1 = fmaxf(m1r, mx1);
                float c0 = __expf(m0r - mn0), c1 = __expf(m1r - mn1);

                uint32_t phL[8], phH[8];
                float ls0 = 0.f, ls1 = 0.f;
                #pragma unroll
                for (int nt = 0; nt < 8; nt++) {
                    float p0 = __expf(S[nt][0] - mn0);
                    float p1 = __expf(S[nt][1] - mn0);
                    float p2 = __expf(S[nt][2] - mn1);
                    float p3 = __expf(S[nt][3] - mn1);
                    ls0 += p0 + p1;
                    ls1 += p2 + p3;
                    phL[nt] = h2u(__floats2half2_rn(p0, p1));
                    phH[nt] = h2u(__floats2half2_rn(p2, p3));
                }
                ls0 += __shfl_xor_sync(0xffffffffu, ls0, 1);
                ls0 += __shfl_xor_sync(0xffffffffu, ls0, 2);
                ls1 += __shfl_xor_sync(0xffffffffu, ls1, 1);
                ls1 += __shfl_xor_sync(0xffffffffu, ls1, 2);
                l0r = l0r * c0 + ls0;
                l1r = l1r * c1 + ls1;
                m0r = mn0; m1r = mn1;

                #pragma unroll
                for (int nt = 0; nt < 8; nt++) {
                    O[nt][0] *= c0; O[nt][1] *= c0;
                    O[nt][2] *= c1; O[nt][3] *= c1;
                }

                // ---- O += P @ V (A = P regs, B = V^T smem) ----
                #pragma unroll
                for (int c = 0; c < 2; c++) {
                    uint4 vb[8];
                    #pragma unroll
                    for (int ntd = 0; ntd < 8; ntd++)
                        vb[ntd] = *(const uint4*)(sVtb + (ntd * 8 + gi) * KVROW + c * 64 + gc * 16);
                    #pragma unroll
                    for (int h = 0; h < 2; h++) {
                        int q0 = 4 * c + 2 * h;
                        uint32_t a0 = phL[q0], a1 = phH[q0];
                        uint32_t a2 = phL[q0 + 1], a3 = phH[q0 + 1];
                        #pragma unroll
                        for (int ntd = 0; ntd < 8; ntd++)
                            mma16(O[ntd], a0, a1, a2, a3,
                                  h ? vb[ntd].z : vb[ntd].x,
                                  h ? vb[ntd].w : vb[ntd].y);
                    }
                }
            }
        }

        float inv0 = 1.f / l0r, inv1 = 1.f / l1r;
        __half* Og = g_att + ((size_t)bh << 17) + ((size_t)qt << 13);
        #pragma unroll
        for (int nt = 0; nt < 8; nt++) {
            int d0 = nt * 8 + 2 * gc;      // even
            int pos = hpos(d0);
            *(__half2*)(Og + i0 * 64 + pos) =
                __floats2half2_rn(O[nt][0] * inv0, O[nt][1] * inv0);
            *(__half2*)(Og + (i0 + 8) * 64 + pos) =
                __floats2half2_rn(O[nt][2] * inv1, O[nt][3] * inv1);
        }
    }
}

// ---------------------------------------------------------------------------
// Kernel 3: proj GEMM (fp16). BK=64 aligns with head dim: stage it == head it.
// ---------------------------------------------------------------------------
__global__ __launch_bounds__(256, 2) void proj_mma_kernel(const float* __restrict__ bias,
                                                          float* __restrict__ out)
{
    extern __shared__ char smc[];
    char* sA = smc;
    char* sB = smc + 2 * HSTG;

    const int tid  = threadIdx.x;
    const int lane = tid & 31;
    const int warp = tid >> 5;
    const int gi = lane >> 2, gc = lane & 3;
    const int wm = (warp >> 2) * 64;
    const int wn = (warp & 3) * 32;
    const int m0 = blockIdx.y * 128, n0 = blockIdx.x * 128;

    const int r0 = tid >> 1, u0 = (tid & 1) * 4;
    const int m = m0 + r0;
    const int bb = m >> 11, tt = m & 2047;
    const __half* gB = g_wprojT + (size_t)(n0 + r0) * CC + u0 * 8;
    char* da = sA + r0 * HROW + u0 * 16;
    char* db = sB + r0 * HROW + u0 * 16;

    float C[4][4][4] = {};

#define PLOAD(s, it_)                                                              \
    {                                                                              \
        const __half* ga = g_att + ((size_t)((bb << 4) + (it_)) << 17)             \
                         + ((size_t)tt << 6) + u0 * 8;                             \
        _Pragma("unroll")                                                          \
        for (int j = 0; j < 4; j++) {                                              \
            cpa16(da + (s) * HSTG + j * 16, ga + j * 8);                           \
            cpa16(db + (s) * HSTG + j * 16, gB + (it_) * 64 + j * 8);              \
        }                                                                          \
        CP_COMMIT;                                                                 \
    }

    PLOAD(0, 0);
    for (int it = 0; it < 16; it++) {
        const int s = it & 1;
        CP_WAIT0;
        __syncthreads();
        if (it + 1 < 16) PLOAD(s ^ 1, it + 1);
        const char* Asb = sA + s * HSTG;
        const char* Bsb = sB + s * HSTG;
        GEMM_COMPUTE16(Asb, Bsb);
    }

    #pragma unroll
    for (int tm = 0; tm < 4; tm++) {
        #pragma unroll
        for (int tn = 0; tn < 4; tn++) {
            #pragma unroll
            for (int e = 0; e < 4; e++) {
                int mm = m0 + wm + tm * 16 + gi + ((e >= 2) ? 8 : 0);
                int n = n0 + wn + tn * 8 + 2 * gc + (e & 1);
                out[(size_t)mm * CC + n] = C[tm][tn][e] + bias[n];
            }
        }
    }
}

// ---------------------------------------------------------------------------
extern "C" void kernel_launch(void* const* d_in, const int* in_sizes, int n_in,
                              void* d_out, int out_size)
{
    const float* x     = (const float*)d_in[0];
    const float* Wqkv  = (const float*)d_in[1];
    const float* bqkv  = (const float*)d_in[2];
    const float* Wproj = (const float*)d_in[3];
    const float* bproj = (const float*)d_in[4];
    float* out = (float*)d_out;

    cudaFuncSetAttribute(qkv_mma_kernel,
                         cudaFuncAttributeMaxDynamicSharedMemorySize, GEMM_SMEM);
    cudaFuncSetAttribute(proj_mma_kernel,
                         cudaFuncAttributeMaxDynamicSharedMemorySize, GEMM_SMEM);
    cudaFuncSetAttribute(attn_mma_kernel,
                         cudaFuncAttributeMaxDynamicSharedMemorySize, ATTN_SMEM);

    __half* xt; __half* wq; __half* wp;
    cudaGetSymbolAddress((void**)&xt, g_xt);
    cudaGetSymbolAddress((void**)&wq, g_wqkvT);
    cudaGetSymbolAddress((void**)&wp, g_wprojT);

    cvt_x_kernel<<<2048, 256>>>(x, xt);                               // 4096x1024
    transpose_h_kernel<<<dim3(96, 32), 128>>>(Wqkv, wq, 3 * CC);      // -> [3072][1024]
    transpose_h_kernel<<<dim3(32, 32), 128>>>(Wproj, wp, CC);         // -> [1024][1024]

    qkv_mma_kernel<<<dim3(24, 32), 256, GEMM_SMEM>>>(bqkv);
    attn_mma_kernel<<<dim3(8, 32), 256, ATTN_SMEM>>>();
    proj_mma_kernel<<<dim3(8, 32), 256, GEMM_SMEM>>>(bproj, out);
}

// round 11
// speedup vs baseline: 1.9107x; 1.1071x over previous
#include <cuda_runtime.h>
#include <cuda_fp16.h>
#include <math.h>
#include <stdint.h>

#define BB 2
#define TT 2048
#define CC 1024
#define NH 16
#define HD 64
#define BH (BB*NH)

// scratch — all fp16, fragment-permuted within 32-element k-chunks
__device__ __half g_q[(size_t)BH * TT * HD];      // [bh][t][d_pos], pre-scaled 1/8
__device__ __half g_k[(size_t)BH * TT * HD];      // [bh][t][d_pos]
__device__ __half g_vt[(size_t)BH * HD * TT];     // [bh][d][t_pos]
__device__ __half g_att[(size_t)BH * TT * HD];    // [bh][t][d_pos]
__device__ __half g_xt[(size_t)BB * TT * CC];     // [m][k_pos]
__device__ __half g_wqkvT[(size_t)3 * CC * CC];   // [n][k_pos]
__device__ __half g_wprojT[(size_t)CC * CC];      // [n][k_pos]

// perm within 32-chunk: k = 16h+8b+2g+l -> pos = g*8 + 4h + 2b + l
__device__ __forceinline__ int hpos(int k) {
    return (k & ~31) + (((k >> 1) & 3) << 3) + (((k >> 4) & 1) << 2)
         + (((k >> 3) & 1) << 1) + (k & 1);
}

__device__ __forceinline__ uint32_t h2u(__half2 h) { return *(uint32_t*)&h; }

__device__ __forceinline__ void mma16(float* c,
                                      uint32_t a0, uint32_t a1, uint32_t a2, uint32_t a3,
                                      uint32_t b0, uint32_t b1) {
    asm volatile(
        "mma.sync.aligned.m16n8k16.row.col.f32.f16.f16.f32 "
        "{%0,%1,%2,%3}, {%4,%5,%6,%7}, {%8,%9}, {%0,%1,%2,%3};"
        : "+f"(c[0]), "+f"(c[1]), "+f"(c[2]), "+f"(c[3])
        : "r"(a0), "r"(a1), "r"(a2), "r"(a3), "r"(b0), "r"(b1));
}

__device__ __forceinline__ void cpa16(void* smem_dst, const void* gptr) {
    unsigned s = (unsigned)__cvta_generic_to_shared(smem_dst);
    asm volatile("cp.async.cg.shared.global [%0], [%1], 16;" :: "r"(s), "l"(gptr));
}
#define CP_COMMIT asm volatile("cp.async.commit_group;")
#define CP_WAIT0  asm volatile("cp.async.wait_group 0;")

// ---------------------------------------------------------------------------
// pre-pass: x (fp32 [m][1024]) -> g_xt fp16 [m][k_pos]
// ---------------------------------------------------------------------------
__global__ __launch_bounds__(256) void cvt_x_kernel(const float* __restrict__ in,
                                                    __half* __restrict__ out)
{
    int gid = blockIdx.x * 256 + threadIdx.x;     // unit of 8 halves
    int row = gid >> 7;
    int uc = gid & 127;
    int cb = (uc >> 2) << 5;                      // chunk base k
    int g = uc & 3;
    const float* src = in + (size_t)row * CC + cb + 2 * g;
    float2 v0 = *(const float2*)(src);
    float2 v1 = *(const float2*)(src + 8);
    float2 v2 = *(const float2*)(src + 16);
    float2 v3 = *(const float2*)(src + 24);
    uint4 o;
    o.x = h2u(__floats2half2_rn(v0.x, v0.y));
    o.y = h2u(__floats2half2_rn(v1.x, v1.y));
    o.z = h2u(__floats2half2_rn(v2.x, v2.y));
    o.w = h2u(__floats2half2_rn(v3.x, v3.y));
    *(uint4*)(out + (size_t)row * CC + cb + g * 8) = o;
}

// pre-pass: W fp32 [K=1024][N] -> out fp16 [N][k_pos] (tiled transpose)
__global__ __launch_bounds__(128) void transpose_h_kernel(const float* __restrict__ in,
                                                          __half* __restrict__ out,
                                                          int N)
{
    __shared__ float t[32][33];
    const int k0 = blockIdx.y << 5, n0 = blockIdx.x << 5;
    const int tid = threadIdx.x;
    #pragma unroll
    for (int i = 0; i < 8; i++) {
        int idx = i * 128 + tid;
        int r = idx >> 5, c = idx & 31;
        t[r][c] = in[(size_t)(k0 + r) * N + n0 + c];
    }
    __syncthreads();
    int nl = tid >> 2, g = tid & 3;
    uint4 o;
    o.x = h2u(__floats2half2_rn(t[2*g][nl],      t[2*g+1][nl]));
    o.y = h2u(__floats2half2_rn(t[2*g+8][nl],    t[2*g+9][nl]));
    o.z = h2u(__floats2half2_rn(t[2*g+16][nl],   t[2*g+17][nl]));
    o.w = h2u(__floats2half2_rn(t[2*g+24][nl],   t[2*g+25][nl]));
    *(uint4*)(out + (size_t)(n0 + nl) * 1024 + k0 + g * 8) = o;
}

// ---------------------------------------------------------------------------
// fp16 GEMM microkernel. Block tile 128x128, BK=64, 2-stage, one sync/iter.
// Row stride 192 B (48 words == 16 mod 32 banks): even/odd rows alternate
// bank halves, gc adds 4-word steps -> conflict-free lds.128.
// ---------------------------------------------------------------------------
#define HROW 192
#define HSTG (128*HROW)         // 24576 B per stage per operand
#define GEMM_SMEM (4*HSTG)      // 98304 B

#define GEMM_COMPUTE16(Asb, Bsb)                                                 \
    _Pragma("unroll")                                                            \
    for (int kc = 0; kc < 2; kc++) {                                             \
        uint4 alo[4], ahi[4], bf[4];                                             \
        _Pragma("unroll")                                                        \
        for (int tm = 0; tm < 4; tm++) {                                         \
            int r = wm + tm * 16 + gi;                                           \
            alo[tm] = *(const uint4*)((Asb) + r * HROW + kc * 64 + gc * 16);     \
            ahi[tm] = *(const uint4*)((Asb) + (r + 8) * HROW + kc * 64 + gc * 16); \
        }                                                                        \
        _Pragma("unroll")                                                        \
        for (int tn = 0; tn < 4; tn++) {                                         \
            int n = wn + tn * 8 + gi;                                            \
            bf[tn] = *(const uint4*)((Bsb) + n * HROW + kc * 64 + gc * 16);      \
        }                                                                        \
        _Pragma("unroll")                                                        \
        for (int tm = 0; tm < 4; tm++)                                           \
            _Pragma("unroll")                                                    \
            for (int tn = 0; tn < 4; tn++) {                                     \
                mma16(C[tm][tn], alo[tm].x, ahi[tm].x, alo[tm].y, ahi[tm].y,     \
                      bf[tn].x, bf[tn].y);                                       \
                mma16(C[tm][tn], alo[tm].z, ahi[tm].z, alo[tm].w, ahi[tm].w,     \
                      bf[tn].z, bf[tn].w);                                       \
            }                                                                    \
    }

// ---------------------------------------------------------------------------
// Kernel 1: QKV GEMM (fp16)
// ---------------------------------------------------------------------------
__global__ __launch_bounds__(256, 2) void qkv_mma_kernel(const float* __restrict__ bias)
{
    extern __shared__ char smc[];
    char* sA = smc;                 // [2][128][192B]
    char* sB = smc + 2 * HSTG;

    const int tid  = threadIdx.x;
    const int lane = tid & 31;
    const int warp = tid >> 5;
    const int gi = lane >> 2, gc = lane & 3;
    const int wm = (warp >> 2) * 64;
    const int wn = (warp & 3) * 32;
    const int m0 = blockIdx.y * 128, n0 = blockIdx.x * 128;

    const int r0 = tid >> 1, u0 = (tid & 1) * 4;     // 2 threads/row, 4 units each
    const __half* gA = g_xt    + (size_t)(m0 + r0) * CC + u0 * 8;
    const __half* gB = g_wqkvT + (size_t)(n0 + r0) * CC + u0 * 8;
    char* da = sA + r0 * HROW + u0 * 16;
    char* db = sB + r0 * HROW + u0 * 16;

    float C[4][4][4] = {};

#define QLOAD(s, kh)                                                   \
    {                                                                  \
        _Pragma("unroll")                                              \
        for (int j = 0; j < 4; j++) {                                  \
            cpa16(da + (s) * HSTG + j * 16, gA + (kh) + j * 8);        \
            cpa16(db + (s) * HSTG + j * 16, gB + (kh) + j * 8);        \
        }                                                              \
        CP_COMMIT;                                                     \
    }

    QLOAD(0, 0);
    for (int it = 0; it < 16; it++) {
        const int s = it & 1;
        CP_WAIT0;
        __syncthreads();
        if (it + 1 < 16) QLOAD(s ^ 1, (it + 1) * 64);
        const char* Asb = sA + s * HSTG;
        const char* Bsb = sB + s * HSTG;
        GEMM_COMPUTE16(Asb, Bsb);
    }

    // epilogue: bias, scatter fp16 into q/k/vt with baked perms
    #pragma unroll
    for (int tm = 0; tm < 4; tm++) {
        #pragma unroll
        for (int tn = 0; tn < 4; tn++) {
            #pragma unroll
            for (int half_ = 0; half_ < 2; half_++) {    // rows gi / gi+8
                int m = m0 + wm + tm * 16 + gi + half_ * 8;
                int n = n0 + wn + tn * 8 + 2 * gc;       // even; pair (n, n+1)
                float v0 = C[tm][tn][half_ * 2 + 0] + bias[n];
                float v1 = C[tm][tn][half_ * 2 + 1] + bias[n + 1];
                int b = m >> 11, t = m & 2047;
                int h = n / 192;
                int r = n - h * 192;
                int d = r & 63;                           // even
                int bh = (b << 4) + h;
                if (r < 64) {
                    __half2 hv = __floats2half2_rn(v0 * 0.125f, v1 * 0.125f);
                    *(__half2*)(g_q + ((size_t)bh << 17) + ((size_t)t << 6) + hpos(d)) = hv;
                } else if (r < 128) {
                    __half2 hv = __floats2half2_rn(v0, v1);
                    *(__half2*)(g_k + ((size_t)bh << 17) + ((size_t)t << 6) + hpos(d)) = hv;
                } else {
                    int tp = hpos(t);
                    g_vt[((size_t)(bh * 64 + d)     << 11) + tp] = __float2half_rn(v0);
                    g_vt[((size_t)(bh * 64 + d + 1) << 11) + tp] = __float2half_rn(v1);
                }
            }
        }
    }
}

// ---------------------------------------------------------------------------
// Kernel 2: causal flash attention (fp16). 256 thr, 128-query tile,
// 64-key tiles, P kept in registers (no smem round-trip).
// ---------------------------------------------------------------------------
#define KVROW 192
#define KVBUF (64*KVROW)         // 12288 B
#define ATTN_SMEM (4*KVBUF)      // 49152 B

__global__ __launch_bounds__(256, 2) void attn_mma_kernel()
{
    extern __shared__ char smc[];
    char* sK  = smc;                   // [2][64 key][192B dim]
    char* sVt = smc + 2 * KVBUF;       // [2][64 dim][192B key]

    const int bh = blockIdx.y;
    const int tid = threadIdx.x;
    const int lane = tid & 31;
    const int warp = tid >> 5;
    const int gi = lane >> 2, gc = lane & 3;
    const int i0 = warp * 16 + gi;

    const __half* Kg  = g_k  + ((size_t)bh << 17);
    const __half* Vtg = g_vt + ((size_t)bh << 17);

    // 64x64 fp16 tile = 512 16B units; 256 threads -> 2 units per tensor
    const int rr = tid >> 2, uu = tid & 3;
#define KV_LOAD(s, kt)                                                        \
    {                                                                         \
        cpa16(sK + (s) * KVBUF + rr * KVROW + uu * 32,                        \
              Kg + (size_t)(((kt) << 6) + rr) * HD + uu * 16);                \
        cpa16(sK + (s) * KVBUF + rr * KVROW + uu * 32 + 16,                   \
              Kg + (size_t)(((kt) << 6) + rr) * HD + uu * 16 + 8);            \
        cpa16(sVt + (s) * KVBUF + rr * KVROW + uu * 32,                       \
              Vtg + ((size_t)rr << 11) + ((kt) << 6) + uu * 16);              \
        cpa16(sVt + (s) * KVBUF + rr * KVROW + uu * 32 + 16,                  \
              Vtg + ((size_t)rr << 11) + ((kt) << 6) + uu * 16 + 8);          \
        CP_COMMIT;                                                            \
    }

    for (int pi = 0; pi < 2; pi++) {
        const int qt = pi ? (15 - (int)blockIdx.x) : (int)blockIdx.x;
        const int ktmax = 2 * qt + 1;
        const __half* Qg = g_q + ((size_t)bh << 17) + ((size_t)qt << 13);

        __syncthreads();   // all warps done with previous pi's buffers
        KV_LOAD(0, 0);

        // Q fragments straight from gmem (read once per pi)
        uint4 qa[2], qb[2];
        #pragma unroll
        for (int qc = 0; qc < 2; qc++) {
            qa[qc] = *(const uint4*)(Qg + i0 * 64 + qc * 32 + gc * 8);
            qb[qc] = *(const uint4*)(Qg + (i0 + 8) * 64 + qc * 32 + gc * 8);
        }

        float O[8][4] = {};
        float m0r = -1e30f, m1r = -1e30f, l0r = 0.f, l1r = 0.f;

        for (int kt = 0; kt <= ktmax; kt++) {
            const int s = kt & 1;
            CP_WAIT0;
            __syncthreads();
            if (kt < ktmax) KV_LOAD(s ^ 1, kt + 1);

            const bool active = (kt * 64 <= qt * 128 + warp * 16 + 15);
            if (active) {
                const char* sKb  = sK + s * KVBUF;
                const char* sVtb = sVt + s * KVBUF;

                // ---- S = Q @ K^T ----
                float S[8][4] = {};
                #pragma unroll
                for (int qc = 0; qc < 2; qc++) {
                    #pragma unroll
                    for (int nt = 0; nt < 8; nt++) {
                        int n = nt * 8 + gi;
                        uint4 kb = *(const uint4*)(sKb + n * KVROW + qc * 64 + gc * 16);
                        mma16(S[nt], qa[qc].x, qb[qc].x, qa[qc].y, qb[qc].y, kb.x, kb.y);
                        mma16(S[nt], qa[qc].z, qb[qc].z, qa[qc].w, qb[qc].w, kb.z, kb.w);
                    }
                }

                if (kt >= 2 * qt) {   // diagonal region: causal mask
                    int ig0 = qt * 128 + i0;
                    #pragma unroll
                    for (int nt = 0; nt < 8; nt++) {
                        int j0 = kt * 64 + nt * 8 + 2 * gc;
                        if (j0 > ig0)         S[nt][0] = -1e30f;
                        if (j0 + 1 > ig0)     S[nt][1] = -1e30f;
                        if (j0 > ig0 + 8)     S[nt][2] = -1e30f;
                        if (j0 + 1 > ig0 + 8) S[nt][3] = -1e30f;
                    }
                }

                // ---- online softmax, P -> registers (fp16 pairs) ----
                float mx0 = -1e30f, mx1 = -1e30f;
                #pragma unroll
                for (int nt = 0; nt < 8; nt++) {
                    mx0 = fmaxf(mx0, fmaxf(S[nt][0], S[nt][1]));
                    mx1 = fmaxf(mx1, fmaxf(S[nt][2], S[nt][3]));
                }
                mx0 = fmaxf(mx0, __shfl_xor_sync(0xffffffffu, mx0, 1));
                mx0 = fmaxf(mx0, __shfl_xor_sync(0xffffffffu, mx0, 2));
                mx1 = fmaxf(mx1, __shfl_xor_sync(0xffffffffu, mx1, 1));
                mx1 = fmaxf(mx1, __shfl_xor_sync(0xffffffffu, mx1, 2));

                float mn0 = fmaxf(m0r, mx0), mn1 = fmaxf(m1r, mx1);
                float c0 = __expf(m0r - mn0), c1 = __expf(m1r - mn1);

                uint32_t phL[8], phH[8];
                float ls0 = 0.f, ls1 = 0.f;
                #pragma unroll
                for (int nt = 0; nt < 8; nt++) {
                    float p0 = __expf(S[nt][0] - mn0);
                    float p1 = __expf(S[nt][1] - mn0);
                    float p2 = __expf(S[nt][2] - mn1);
                    float p3 = __expf(S[nt][3] - mn1);
                    ls0 += p0 + p1;
                    ls1 += p2 + p3;
                    phL[nt] = h2u(__floats2half2_rn(p0, p1));
                    phH[nt] = h2u(__floats2half2_rn(p2, p3));
                }
                ls0 += __shfl_xor_sync(0xffffffffu, ls0, 1);
                ls0 += __shfl_xor_sync(0xffffffffu, ls0, 2);
                ls1 += __shfl_xor_sync(0xffffffffu, ls1, 1);
                ls1 += __shfl_xor_sync(0xffffffffu, ls1, 2);
                l0r = l0r * c0 + ls0;
                l1r = l1r * c1 + ls1;
                m0r = mn0; m1r = mn1;

                #pragma unroll
                for (int nt = 0; nt < 8; nt++) {
                    O[nt][0] *= c0; O[nt][1] *= c0;
                    O[nt][2] *= c1; O[nt][3] *= c1;
                }

                // ---- O += P @ V (A = P regs, B = V^T smem) ----
                #pragma unroll
                for (int c = 0; c < 2; c++) {
                    uint4 vb[8];
                    #pragma unroll
                    for (int ntd = 0; ntd < 8; ntd++)
                        vb[ntd] = *(const uint4*)(sVtb + (ntd * 8 + gi) * KVROW + c * 64 + gc * 16);
                    #pragma unroll
                    for (int h = 0; h < 2; h++) {
                        int q0 = 4 * c + 2 * h;
                        uint32_t a0 = phL[q0], a1 = phH[q0];
                        uint32_t a2 = phL[q0 + 1], a3 = phH[q0 + 1];
                        #pragma unroll
                        for (int ntd = 0; ntd < 8; ntd++)
                            mma16(O[ntd], a0, a1, a2, a3,
                                  h ? vb[ntd].z : vb[ntd].x,
                                  h ? vb[ntd].w : vb[ntd].y);
                    }
                }
            }
        }

        float inv0 = 1.f / l0r, inv1 = 1.f / l1r;
        __half* Og = g_att + ((size_t)bh << 17) + ((size_t)qt << 13);
        #pragma unroll
        for (int nt = 0; nt < 8; nt++) {
            int d0 = nt * 8 + 2 * gc;      // even
            int pos = hpos(d0);
            *(__half2*)(Og + i0 * 64 + pos) =
                __floats2half2_rn(O[nt][0] * inv0, O[nt][1] * inv0);
            *(__half2*)(Og + (i0 + 8) * 64 + pos) =
                __floats2half2_rn(O[nt][2] * inv1, O[nt][3] * inv1);
        }
    }
}

// ---------------------------------------------------------------------------
// Kernel 3: proj GEMM (fp16). BK=64 aligns with head dim: stage it == head it.
// ---------------------------------------------------------------------------
__global__ __launch_bounds__(256, 2) void proj_mma_kernel(const float* __restrict__ bias,
                                                          float* __restrict__ out)
{
    extern __shared__ char smc[];
    char* sA = smc;
    char* sB = smc + 2 * HSTG;

    const int tid  = threadIdx.x;
    const int lane = tid & 31;
    const int warp = tid >> 5;
    const int gi = lane >> 2, gc = lane & 3;
    const int wm = (warp >> 2) * 64;
    const int wn = (warp & 3) * 32;
    const int m0 = blockIdx.y * 128, n0 = blockIdx.x * 128;

    const int r0 = tid >> 1, u0 = (tid & 1) * 4;
    const int m = m0 + r0;
    const int bb = m >> 11, tt = m & 2047;
    const __half* gB = g_wprojT + (size_t)(n0 + r0) * CC + u0 * 8;
    char* da = sA + r0 * HROW + u0 * 16;
    char* db = sB + r0 * HROW + u0 * 16;

    float C[4][4][4] = {};

#define PLOAD(s, it_)                                                              \
    {                                                                              \
        const __half* ga = g_att + ((size_t)((bb << 4) + (it_)) << 17)             \
                         + ((size_t)tt << 6) + u0 * 8;                             \
        _Pragma("unroll")                                                          \
        for (int j = 0; j < 4; j++) {                                              \
            cpa16(da + (s) * HSTG + j * 16, ga + j * 8);                           \
            cpa16(db + (s) * HSTG + j * 16, gB + (it_) * 64 + j * 8);              \
        }                                                                          \
        CP_COMMIT;                                                                 \
    }

    PLOAD(0, 0);
    for (int it = 0; it < 16; it++) {
        const int s = it & 1;
        CP_WAIT0;
        __syncthreads();
        if (it + 1 < 16) PLOAD(s ^ 1, it + 1);
        const char* Asb = sA + s * HSTG;
        const char* Bsb = sB + s * HSTG;
        GEMM_COMPUTE16(Asb, Bsb);
    }

    #pragma unroll
    for (int tm = 0; tm < 4; tm++) {
        #pragma unroll
        for (int tn = 0; tn < 4; tn++) {
            #pragma unroll
            for (int e = 0; e < 4; e++) {
                int mm = m0 + wm + tm * 16 + gi + ((e >= 2) ? 8 : 0);
                int n = n0 + wn + tn * 8 + 2 * gc + (e & 1);
                out[(size_t)mm * CC + n] = C[tm][tn][e] + bias[n];
            }
        }
    }
}

// ---------------------------------------------------------------------------
extern "C" void kernel_launch(void* const* d_in, const int* in_sizes, int n_in,
                              void* d_out, int out_size)
{
    const float* x     = (const float*)d_in[0];
    const float* Wqkv  = (const float*)d_in[1];
    const float* bqkv  = (const float*)d_in[2];
    const float* Wproj = (const float*)d_in[3];
    const float* bproj = (const float*)d_in[4];
    float* out = (float*)d_out;

    cudaFuncSetAttribute(qkv_mma_kernel,
                         cudaFuncAttributeMaxDynamicSharedMemorySize, GEMM_SMEM);
    cudaFuncSetAttribute(proj_mma_kernel,
                         cudaFuncAttributeMaxDynamicSharedMemorySize, GEMM_SMEM);
    cudaFuncSetAttribute(attn_mma_kernel,
                         cudaFuncAttributeMaxDynamicSharedMemorySize, ATTN_SMEM);

    __half* xt; __half* wq; __half* wp;
    cudaGetSymbolAddress((void**)&xt, g_xt);
    cudaGetSymbolAddress((void**)&wq, g_wqkvT);
    cudaGetSymbolAddress((void**)&wp, g_wprojT);

    cvt_x_kernel<<<2048, 256>>>(x, xt);                               // 4096x1024
    transpose_h_kernel<<<dim3(96, 32), 128>>>(Wqkv, wq, 3 * CC);      // -> [3072][1024]
    transpose_h_kernel<<<dim3(32, 32), 128>>>(Wproj, wp, CC);         // -> [1024][1024]

    qkv_mma_kernel<<<dim3(24, 32), 256, GEMM_SMEM>>>(bqkv);
    attn_mma_kernel<<<dim3(8, 32), 256, ATTN_SMEM>>>();
    proj_mma_kernel<<<dim3(8, 32), 256, GEMM_SMEM>>>(bproj, out);
}

// round 12
// speedup vs baseline: 2.6074x; 1.3646x over previous
#include <cuda_runtime.h>
#include <cuda_fp16.h>
#include <math.h>
#include <stdint.h>

#define BB 2
#define TT 2048
#define CC 1024
#define NH 16
#define HD 64
#define BH (BB*NH)

// scratch — fp16, fragment-permuted + row-parity chunk-swizzled, TILE-PACKED
__device__ __half g_q[(size_t)BH * TT * HD];      // [bh][t][d_pos] (no swizzle; LDG reads)
__device__ __half g_k[(size_t)BH * TT * HD];      // [bh][t][d_pos ^ ((t&1)<<5)] (tile-contig per 64 t)
__device__ __half g_vt[(size_t)BH * HD * TT];     // [bh][kt][d][t_pos ^ ((d&1)<<5)] tiles of 64x64
__device__ __half g_att[(size_t)BH * TT * HD];    // [bh][t][d_pos ^ ((t&1)<<5)]
__device__ __half g_xt[(size_t)BB * TT * CC];     // [mt*16+kt][128][64] tiles, row-swizzled
__device__ __half g_wqkvT[(size_t)3 * CC * CC];   // [nt*16+kt][128][64] tiles
__device__ __half g_wprojT[(size_t)CC * CC];      // [nt*16+kt][128][64] tiles

// perm within 32-chunk: k = 16h+8b+2g+l -> pos = g*8 + 4h + 2b + l
__device__ __forceinline__ int hpos(int k) {
    return (k & ~31) + (((k >> 1) & 3) << 3) + (((k >> 4) & 1) << 2)
         + (((k >> 3) & 1) << 1) + (k & 1);
}

__device__ __forceinline__ uint32_t h2u(__half2 h) { return *(uint32_t*)&h; }

__device__ __forceinline__ uint32_t smem_to_u32(const void* p) {
    uint32_t a;
    asm("{ .reg .u64 t; cvta.to.shared.u64 t, %1; cvt.u32.u64 %0, t; }" : "=r"(a) : "l"(p));
    return a;
}

__device__ __forceinline__ void mma16(float* c,
                                      uint32_t a0, uint32_t a1, uint32_t a2, uint32_t a3,
                                      uint32_t b0, uint32_t b1) {
    asm volatile(
        "mma.sync.aligned.m16n8k16.row.col.f32.f16.f16.f32 "
        "{%0,%1,%2,%3}, {%4,%5,%6,%7}, {%8,%9}, {%0,%1,%2,%3};"
        : "+f"(c[0]), "+f"(c[1]), "+f"(c[2]), "+f"(c[3])
        : "r"(a0), "r"(a1), "r"(a2), "r"(a3), "r"(b0), "r"(b1));
}

// ---- bulk copy + mbarrier ----
__device__ __forceinline__ void bulk_g2s(uint32_t dst, const void* src, uint32_t bytes,
                                         uint32_t mbar) {
    asm volatile(
        "cp.async.bulk.shared::cluster.global.mbarrier::complete_tx::bytes [%0], [%1], %2, [%3];"
        :: "r"(dst), "l"(src), "r"(bytes), "r"(mbar) : "memory");
}
#define MBARRIER_INIT(mbar, cnt) \
    asm volatile("mbarrier.init.shared.b64 [%0], %1;" \
                 :: "r"((uint32_t)(mbar)), "r"((uint32_t)(cnt)) : "memory")
#define MBARRIER_EXPECT_TX(mbar, bytes) \
    asm volatile("mbarrier.arrive.expect_tx.shared.b64 _, [%0], %1;" \
                 :: "r"((uint32_t)(mbar)), "r"((uint32_t)(bytes)) : "memory")
#define MBARRIER_WAIT_PARITY(mbar_smem_addr, phase_parity) do { \
    uint32_t _mbar = (uint32_t)(mbar_smem_addr); \
    uint32_t _parity = (uint32_t)(phase_parity); \
    uint32_t _done; \
    asm volatile( \
        "{\n\t.reg .pred p;\n\t" \
        "mbarrier.try_wait.parity.acquire.cta.shared::cta.b64 p, [%1], %2;\n\t" \
        "selp.b32 %0, 1, 0, p;\n\t}" \
        : "=r"(_done) : "r"(_mbar), "r"(_parity) : "memory"); \
    if (!_done) { \
        asm volatile( \
            "{\n\t.reg .pred P1;\n\t" \
            "WAIT_LOOP_%=:\n\t" \
            "mbarrier.try_wait.parity.acquire.cta.shared::cta.b64 P1, [%0], %1, 0x989680;\n\t" \
            "@P1 bra.uni WAIT_DONE_%=;\n\t" \
            "bra.uni WAIT_LOOP_%=;\n\t" \
            "WAIT_DONE_%=:\n\t}" \
            :: "r"(_mbar), "r"(_parity) : "memory"); \
    } \
} while(0)

// ---------------------------------------------------------------------------
// pre-pass: x fp32 [m][1024] -> g_xt fp16 tiled [mt*16+kt][128][64] swizzled
// ---------------------------------------------------------------------------
__global__ __launch_bounds__(256) void cvt_x_kernel(const float* __restrict__ in,
                                                    __half* __restrict__ out)
{
    int gid = blockIdx.x * 256 + threadIdx.x;     // unit of 8 halves
    int row = gid >> 7;
    int uc = gid & 127;
    int cb = (uc >> 2) << 5;                      // chunk base k (mult of 32)
    int g = uc & 3;
    const float* src = in + (size_t)row * CC + cb + 2 * g;
    float2 v0 = *(const float2*)(src);
    float2 v1 = *(const float2*)(src + 8);
    float2 v2 = *(const float2*)(src + 16);
    float2 v3 = *(const float2*)(src + 24);
    uint4 o;
    o.x = h2u(__floats2half2_rn(v0.x, v0.y));
    o.y = h2u(__floats2half2_rn(v1.x, v1.y));
    o.z = h2u(__floats2half2_rn(v2.x, v2.y));
    o.w = h2u(__floats2half2_rn(v3.x, v3.y));
    int mt = row >> 7, kt = cb >> 6, r = row & 127;
    int ch = ((cb >> 5) & 1) ^ (r & 1);
    *(uint4*)(out + ((size_t)(mt * 16 + kt) << 13) + (r << 6) + (ch << 5) + g * 8) = o;
}

// pre-pass: W fp32 [K=1024][N] -> tiled fp16 [nt*16+kt][128][64] swizzled
__global__ __launch_bounds__(128) void transpose_h_kernel(const float* __restrict__ in,
                                                          __half* __restrict__ out,
                                                          int N)
{
    __shared__ float t[32][33];
    const int k0 = blockIdx.y << 5, n0 = blockIdx.x << 5;
    const int tid = threadIdx.x;
    #pragma unroll
    for (int i = 0; i < 8; i++) {
        int idx = i * 128 + tid;
        int r = idx >> 5, c = idx & 31;
        t[r][c] = in[(size_t)(k0 + r) * N + n0 + c];
    }
    __syncthreads();
    int nl = tid >> 2, g = tid & 3;
    uint4 o;
    o.x = h2u(__floats2half2_rn(t[2*g][nl],      t[2*g+1][nl]));
    o.y = h2u(__floats2half2_rn(t[2*g+8][nl],    t[2*g+9][nl]));
    o.z = h2u(__floats2half2_rn(t[2*g+16][nl],   t[2*g+17][nl]));
    o.w = h2u(__floats2half2_rn(t[2*g+24][nl],   t[2*g+25][nl]));
    int n = n0 + nl;
    int nt = n >> 7, kt = k0 >> 6, r = n & 127;
    int ch = ((k0 >> 5) & 1) ^ (r & 1);
    *(uint4*)(out + ((size_t)(nt * 16 + kt) << 13) + (r << 6) + (ch << 5) + g * 8) = o;
}

// ---------------------------------------------------------------------------
// fp16 GEMM compute. Tiles [128 rows][128 B], row-parity chunk swizzle.
// sxor = (gi&1)<<6 (bytes).
// ---------------------------------------------------------------------------
#define TILE_B 16384

#define GEMM_COMPUTE16(Asb, Bsb)                                                 \
    _Pragma("unroll")                                                            \
    for (int kc = 0; kc < 2; kc++) {                                             \
        const int co = (kc * 64 + gc * 16) ^ sxor;                               \
        uint4 alo[4], ahi[4], bf[4];                                             \
        _Pragma("unroll")                                                        \
        for (int tm = 0; tm < 4; tm++) {                                         \
            int r = wm + tm * 16 + gi;                                           \
            alo[tm] = *(const uint4*)((Asb) + r * 128 + co);                     \
            ahi[tm] = *(const uint4*)((Asb) + (r + 8) * 128 + co);               \
        }                                                                        \
        _Pragma("unroll")                                                        \
        for (int tn = 0; tn < 4; tn++) {                                         \
            int n = wn + tn * 8 + gi;                                            \
            bf[tn] = *(const uint4*)((Bsb) + n * 128 + co);                      \
        }                                                                        \
        _Pragma("unroll")                                                        \
        for (int tm = 0; tm < 4; tm++)                                           \
            _Pragma("unroll")                                                    \
            for (int tn = 0; tn < 4; tn++) {                                     \
                mma16(C[tm][tn], alo[tm].x, ahi[tm].x, alo[tm].y, ahi[tm].y,     \
                      bf[tn].x, bf[tn].y);                                       \
                mma16(C[tm][tn], alo[tm].z, ahi[tm].z, alo[tm].w, ahi[tm].w,     \
                      bf[tn].z, bf[tn].w);                                       \
            }                                                                    \
    }

// smem: mbars at 0/8/16, A tiles at 128 + s*TILE_B, B tiles at 128+3*TILE_B + s*TILE_B
#define GEMM_SMEM (128 + 6*TILE_B)   // 98432 B

// ---------------------------------------------------------------------------
// Kernel 1: QKV GEMM (fp16, bulk-copy 3-stage)
// ---------------------------------------------------------------------------
__global__ __launch_bounds__(256, 2) void qkv_mma_kernel(const float* __restrict__ bias)
{
    extern __shared__ char smc[];
    const uint32_t sb = smem_to_u32(smc);
    const char* tA = smc + 128;
    const char* tB = smc + 128 + 3 * TILE_B;

    const int tid  = threadIdx.x;
    const int lane = tid & 31;
    const int warp = tid >> 5;
    const int gi = lane >> 2, gc = lane & 3;
    const int sxor = (gi & 1) << 6;
    const int wm = (warp >> 2) * 64;
    const int wn = (warp & 3) * 32;
    const int m0 = blockIdx.y * 128, n0 = blockIdx.x * 128;

    if (tid == 0) {
        MBARRIER_INIT(sb + 0, 1);
        MBARRIER_INIT(sb + 8, 1);
        MBARRIER_INIT(sb + 16, 1);
    }
    __syncthreads();

#define Q_ISSUE(s, kt)                                                          \
    {                                                                           \
        MBARRIER_EXPECT_TX(sb + 8 * (s), 2 * TILE_B);                           \
        bulk_g2s(sb + 128 + (s) * TILE_B,                                       \
                 g_xt + ((size_t)(blockIdx.y * 16 + (kt)) << 13), TILE_B,       \
                 sb + 8 * (s));                                                 \
        bulk_g2s(sb + 128 + 3 * TILE_B + (s) * TILE_B,                          \
                 g_wqkvT + ((size_t)(blockIdx.x * 16 + (kt)) << 13), TILE_B,    \
                 sb + 8 * (s));                                                 \
    }

    if (tid == 0) { Q_ISSUE(0, 0); Q_ISSUE(1, 1); }

    float C[4][4][4] = {};
    int ph0 = 0, ph1 = 0, ph2 = 0;

    for (int it = 0; it < 16; it++) {
        const int s = it % 3;
        int ph = (s == 0) ? ph0 : (s == 1) ? ph1 : ph2;
        MBARRIER_WAIT_PARITY(sb + 8 * s, ph);
        if (s == 0) ph0 ^= 1; else if (s == 1) ph1 ^= 1; else ph2 ^= 1;
        __syncthreads();           // all warps done reading stage (it+2)%3 (iter it-1)
        if (tid == 0 && it + 2 < 16) { int s2 = (it + 2) % 3; Q_ISSUE(s2, it + 2); }
        const char* Asb = tA + s * TILE_B;
        const char* Bsb = tB + s * TILE_B;
        GEMM_COMPUTE16(Asb, Bsb);
    }

    // epilogue: bias, scatter fp16 into q/k/vt (swizzled layouts)
    #pragma unroll
    for (int tm = 0; tm < 4; tm++) {
        #pragma unroll
        for (int tn = 0; tn < 4; tn++) {
            #pragma unroll
            for (int half_ = 0; half_ < 2; half_++) {
                int m = m0 + wm + tm * 16 + gi + half_ * 8;
                int n = n0 + wn + tn * 8 + 2 * gc;       // even; pair (n, n+1)
                float v0 = C[tm][tn][half_ * 2 + 0] + bias[n];
                float v1 = C[tm][tn][half_ * 2 + 1] + bias[n + 1];
                int b = m >> 11, t = m & 2047;
                int h = n / 192;
                int r = n - h * 192;
                int d = r & 63;                           // even
                int bh = (b << 4) + h;
                if (r < 64) {
                    __half2 hv = __floats2half2_rn(v0 * 0.125f, v1 * 0.125f);
                    *(__half2*)(g_q + ((size_t)bh << 17) + ((size_t)t << 6) + hpos(d)) = hv;
                } else if (r < 128) {
                    __half2 hv = __floats2half2_rn(v0, v1);
                    int pos = hpos(d) ^ ((t & 1) << 5);
                    *(__half2*)(g_k + ((size_t)bh << 17) + ((size_t)t << 6) + pos) = hv;
                } else {
                    size_t tbase = ((size_t)(bh * 32 + (t >> 6)) << 12);
                    int tp = hpos(t & 63);
                    g_vt[tbase + ((size_t)d << 6) + tp]              = __float2half_rn(v0);
                    g_vt[tbase + ((size_t)(d + 1) << 6) + (tp ^ 32)] = __float2half_rn(v1);
                }
            }
        }
    }
}

// ---------------------------------------------------------------------------
// Kernel 2: causal flash attention (fp16, bulk-copy 2-stage, P in registers)
// ---------------------------------------------------------------------------
#define KTILE_B 8192
#define ATTN_SMEM (128 + 4*KTILE_B)   // 32896 B

__global__ __launch_bounds__(256, 2) void attn_mma_kernel()
{
    extern __shared__ char smc[];
    const uint32_t sb = smem_to_u32(smc);
    const char* tK  = smc + 128;                 // [2][8192]
    const char* tVt = smc + 128 + 2 * KTILE_B;   // [2][8192]

    const int bh = blockIdx.y;
    const int tid = threadIdx.x;
    const int lane = tid & 31;
    const int warp = tid >> 5;
    const int gi = lane >> 2, gc = lane & 3;
    const int sxor = (gi & 1) << 6;
    const int i0 = warp * 16 + gi;

    const __half* Kg  = g_k  + ((size_t)bh << 17);
    const __half* Vtg = g_vt + ((size_t)bh << 17);

    if (tid == 0) { MBARRIER_INIT(sb + 0, 1); MBARRIER_INIT(sb + 8, 1); }
    __syncthreads();

    int islot = 0, wslot = 0, phw0 = 0, phw1 = 0;

#define A_ISSUE(kt)                                                             \
    {                                                                           \
        int s_ = islot & 1;                                                     \
        if (tid == 0) {                                                         \
            MBARRIER_EXPECT_TX(sb + 8 * s_, 2 * KTILE_B);                       \
            bulk_g2s(sb + 128 + s_ * KTILE_B, Kg + ((size_t)(kt) << 12),        \
                     KTILE_B, sb + 8 * s_);                                     \
            bulk_g2s(sb + 128 + 2 * KTILE_B + s_ * KTILE_B,                     \
                     Vtg + ((size_t)(kt) << 12), KTILE_B, sb + 8 * s_);         \
        }                                                                       \
        islot++;                                                                \
    }

    for (int pi = 0; pi < 2; pi++) {
        const int qt = pi ? (15 - (int)blockIdx.x) : (int)blockIdx.x;
        const int ktmax = 2 * qt + 1;
        const __half* Qg = g_q + ((size_t)bh << 17) + ((size_t)qt << 13);

        __syncthreads();   // all warps done with previous pi's stage reads
        A_ISSUE(0);

        uint4 qa[2], qb[2];
        #pragma unroll
        for (int qc = 0; qc < 2; qc++) {
            qa[qc] = *(const uint4*)(Qg + i0 * 64 + qc * 32 + gc * 8);
            qb[qc] = *(const uint4*)(Qg + (i0 + 8) * 64 + qc * 32 + gc * 8);
        }

        float O[8][4] = {};
        float m0r = -1e30f, m1r = -1e30f, l0r = 0.f, l1r = 0.f;

        for (int kt = 0; kt <= ktmax; kt++) {
            const int s = wslot & 1;
            int ph = s ? phw1 : phw0;
            MBARRIER_WAIT_PARITY(sb + 8 * s, ph);
            if (s) phw1 ^= 1; else phw0 ^= 1;
            wslot++;
            __syncthreads();   // all warps done reading stage s^1 (iter kt-1)
            if (kt < ktmax) A_ISSUE(kt + 1);

            const bool active = (kt * 64 <= qt * 128 + warp * 16 + 15);
            if (active) {
                const char* sKb  = tK + s * KTILE_B;
                const char* sVtb = tVt + s * KTILE_B;

                // ---- S = Q @ K^T ----
                float S[8][4] = {};
                #pragma unroll
                for (int qc = 0; qc < 2; qc++) {
                    const int co = (qc * 64 + gc * 16) ^ sxor;
                    #pragma unroll
                    for (int nt = 0; nt < 8; nt++) {
                        int n = nt * 8 + gi;
                        uint4 kb = *(const uint4*)(sKb + n * 128 + co);
                        mma16(S[nt], qa[qc].x, qb[qc].x, qa[qc].y, qb[qc].y, kb.x, kb.y);
                        mma16(S[nt], qa[qc].z, qb[qc].z, qa[qc].w, qb[qc].w, kb.z, kb.w);
                    }
                }

                if (kt >= 2 * qt) {   // diagonal region: causal mask
                    int ig0 = qt * 128 + i0;
                    #pragma unroll
                    for (int nt = 0; nt < 8; nt++) {
                        int j0 = kt * 64 + nt * 8 + 2 * gc;
                        if (j0 > ig0)         S[nt][0] = -1e30f;
                        if (j0 + 1 > ig0)     S[nt][1] = -1e30f;
                        if (j0 > ig0 + 8)     S[nt][2] = -1e30f;
                        if (j0 + 1 > ig0 + 8) S[nt][3] = -1e30f;
                    }
                }

                // ---- online softmax, P -> registers ----
                float mx0 = -1e30f, mx1 = -1e30f;
                #pragma unroll
                for (int nt = 0; nt < 8; nt++) {
                    mx0 = fmaxf(mx0, fmaxf(S[nt][0], S[nt][1]));
                    mx1 = fmaxf(mx1, fmaxf(S[nt][2], S[nt][3]));
                }
                mx0 = fmaxf(mx0, __shfl_xor_sync(0xffffffffu, mx0, 1));
                mx0 = fmaxf(mx0, __shfl_xor_sync(0xffffffffu, mx0, 2));
                mx1 = fmaxf(mx1, __shfl_xor_sync(0xffffffffu, mx1, 1));
                mx1 = fmaxf(mx1, __shfl_xor_sync(0xffffffffu, mx1, 2));

                float mn0 = fmaxf(m0r, mx0), mn1 = fmaxf(m1r, mx1);
                float c0 = __expf(m0r - mn0), c1 = __expf(m1r - mn1);

                uint32_t phL[8], phH[8];
                float ls0 = 0.f, ls1 = 0.f;
                #pragma unroll
                for (int nt = 0; nt < 8; nt++) {
                    float p0 = __expf(S[nt][0] - mn0);
                    float p1 = __expf(S[nt][1] - mn0);
                    float p2 = __expf(S[nt][2] - mn1);
                    float p3 = __expf(S[nt][3] - mn1);
                    ls0 += p0 + p1;
                    ls1 += p2 + p3;
                    phL[nt] = h2u(__floats2half2_rn(p0, p1));
                    phH[nt] = h2u(__floats2half2_rn(p2, p3));
                }
                ls0 += __shfl_xor_sync(0xffffffffu, ls0, 1);
                ls0 += __shfl_xor_sync(0xffffffffu, ls0, 2);
                ls1 += __shfl_xor_sync(0xffffffffu, ls1, 1);
                ls1 += __shfl_xor_sync(0xffffffffu, ls1, 2);
                l0r = l0r * c0 + ls0;
                l1r = l1r * c1 + ls1;
                m0r = mn0; m1r = mn1;

                #pragma unroll
                for (int nt = 0; nt < 8; nt++) {
                    O[nt][0] *= c0; O[nt][1] *= c0;
                    O[nt][2] *= c1; O[nt][3] *= c1;
                }

                // ---- O += P @ V ----
                #pragma unroll
                for (int c = 0; c < 2; c++) {
                    const int co = (c * 64 + gc * 16) ^ sxor;
                    uint4 vb[8];
                    #pragma unroll
                    for (int ntd = 0; ntd < 8; ntd++)
                        vb[ntd] = *(const uint4*)(sVtb + (ntd * 8 + gi) * 128 + co);
                    #pragma unroll
                    for (int h = 0; h < 2; h++) {
                        int q0 = 4 * c + 2 * h;
                        uint32_t a0 = phL[q0], a1 = phH[q0];
                        uint32_t a2 = phL[q0 + 1], a3 = phH[q0 + 1];
                        #pragma unroll
                        for (int ntd = 0; ntd < 8; ntd++)
                            mma16(O[ntd], a0, a1, a2, a3,
                                  h ? vb[ntd].z : vb[ntd].x,
                                  h ? vb[ntd].w : vb[ntd].y);
                    }
                }
            }
        }

        float inv0 = 1.f / l0r, inv1 = 1.f / l1r;
        __half* Og = g_att + ((size_t)bh << 17) + ((size_t)qt << 13);
        #pragma unroll
        for (int nt = 0; nt < 8; nt++) {
            int d0 = nt * 8 + 2 * gc;      // even
            int pos = hpos(d0) ^ ((i0 & 1) << 5);   // t parity == i0 parity
            *(__half2*)(Og + i0 * 64 + pos) =
                __floats2half2_rn(O[nt][0] * inv0, O[nt][1] * inv0);
            *(__half2*)(Og + (i0 + 8) * 64 + pos) =
                __floats2half2_rn(O[nt][2] * inv1, O[nt][3] * inv1);
        }
    }
}

// ---------------------------------------------------------------------------
// Kernel 3: proj GEMM (fp16, bulk-copy 3-stage). iter == head index.
// ---------------------------------------------------------------------------
__global__ __launch_bounds__(256, 2) void proj_mma_kernel(const float* __restrict__ bias,
                                                          float* __restrict__ out)
{
    extern __shared__ char smc[];
    const uint32_t sb = smem_to_u32(smc);
    const char* tA = smc + 128;
    const char* tB = smc + 128 + 3 * TILE_B;

    const int tid  = threadIdx.x;
    const int lane = tid & 31;
    const int warp = tid >> 5;
    const int gi = lane >> 2, gc = lane & 3;
    const int sxor = (gi & 1) << 6;
    const int wm = (warp >> 2) * 64;
    const int wn = (warp & 3) * 32;
    const int m0 = blockIdx.y * 128, n0 = blockIdx.x * 128;
    const int bb = m0 >> 11, t0 = m0 & 2047;

    if (tid == 0) {
        MBARRIER_INIT(sb + 0, 1);
        MBARRIER_INIT(sb + 8, 1);
        MBARRIER_INIT(sb + 16, 1);
    }
    __syncthreads();

#define P_ISSUE(s, it_)                                                          \
    {                                                                            \
        MBARRIER_EXPECT_TX(sb + 8 * (s), 2 * TILE_B);                            \
        bulk_g2s(sb + 128 + (s) * TILE_B,                                        \
                 g_att + ((size_t)((bb << 4) + (it_)) << 17) + (size_t)t0 * 64,  \
                 TILE_B, sb + 8 * (s));                                          \
        bulk_g2s(sb + 128 + 3 * TILE_B + (s) * TILE_B,                           \
                 g_wprojT + ((size_t)(blockIdx.x * 16 + (it_)) << 13), TILE_B,   \
                 sb + 8 * (s));                                                  \
    }

    if (tid == 0) { P_ISSUE(0, 0); P_ISSUE(1, 1); }

    float C[4][4][4] = {};
    int ph0 = 0, ph1 = 0, ph2 = 0;

    for (int it = 0; it < 16; it++) {
        const int s = it % 3;
        int ph = (s == 0) ? ph0 : (s == 1) ? ph1 : ph2;
        MBARRIER_WAIT_PARITY(sb + 8 * s, ph);
        if (s == 0) ph0 ^= 1; else if (s == 1) ph1 ^= 1; else ph2 ^= 1;
        __syncthreads();
        if (tid == 0 && it + 2 < 16) { int s2 = (it + 2) % 3; P_ISSUE(s2, it + 2); }
        const char* Asb = tA + s * TILE_B;
        const char* Bsb = tB + s * TILE_B;
        GEMM_COMPUTE16(Asb, Bsb);
    }

    #pragma unroll
    for (int tm = 0; tm < 4; tm++) {
        #pragma unroll
        for (int tn = 0; tn < 4; tn++) {
            #pragma unroll
            for (int e = 0; e < 4; e++) {
                int mm = m0 + wm + tm * 16 + gi + ((e >= 2) ? 8 : 0);
                int n = n0 + wn + tn * 8 + 2 * gc + (e & 1);
                out[(size_t)mm * CC + n] = C[tm][tn][e] + bias[n];
            }
        }
    }
}

// ---------------------------------------------------------------------------
extern "C" void kernel_launch(void* const* d_in, const int* in_sizes, int n_in,
                              void* d_out, int out_size)
{
    const float* x     = (const float*)d_in[0];
    const float* Wqkv  = (const float*)d_in[1];
    const float* bqkv  = (const float*)d_in[2];
    const float* Wproj = (const float*)d_in[3];
    const float* bproj = (const float*)d_in[4];
    float* out = (float*)d_out;

    cudaFuncSetAttribute(qkv_mma_kernel,
                         cudaFuncAttributeMaxDynamicSharedMemorySize, GEMM_SMEM);
    cudaFuncSetAttribute(proj_mma_kernel,
                         cudaFuncAttributeMaxDynamicSharedMemorySize, GEMM_SMEM);
    cudaFuncSetAttribute(attn_mma_kernel,
                         cudaFuncAttributeMaxDynamicSharedMemorySize, ATTN_SMEM);

    __half* xt; __half* wq; __half* wp;
    cudaGetSymbolAddress((void**)&xt, g_xt);
    cudaGetSymbolAddress((void**)&wq, g_wqkvT);
    cudaGetSymbolAddress((void**)&wp, g_wprojT);

    cvt_x_kernel<<<2048, 256>>>(x, xt);
    transpose_h_kernel<<<dim3(96, 32), 128>>>(Wqkv, wq, 3 * CC);
    transpose_h_kernel<<<dim3(32, 32), 128>>>(Wproj, wp, CC);

    qkv_mma_kernel<<<dim3(24, 32), 256, GEMM_SMEM>>>(bqkv);
    attn_mma_kernel<<<dim3(8, 32), 256, ATTN_SMEM>>>();
    proj_mma_kernel<<<dim3(8, 32), 256, GEMM_SMEM>>>(bproj, out);
}